// round 1
// baseline (speedup 1.0000x reference)
#include <cuda_runtime.h>

#define HDIM   256
#define NSUB   32768
#define NGLOB  65536
#define SSEG   1024

// ---------------- scratch (device globals; no allocation allowed) ----------------
__device__ float g_h_sub[NSUB * HDIM];
__device__ float g_agg_sub[NSUB * HDIM];
__device__ float g_dis_sub[NSUB];
__device__ float g_pooled[SSEG * HDIM];
__device__ float g_cnt[SSEG];
__device__ float g_h_glob[NGLOB * HDIM];
__device__ float g_agg_glob[NGLOB * HDIM];
__device__ float g_dis_glob[NGLOB];
__device__ float g_p2[SSEG * HDIM];
__device__ float g_gemb[HDIM];
__device__ float g_gcnt[1];

// ---------------- tiny utility kernels ----------------
__global__ void k_zero_misc() {
    int i = blockIdx.x * blockDim.x + threadIdx.x;
    if (i < SSEG * HDIM) g_pooled[i] = 0.0f;
    if (i < SSEG)        g_cnt[i]    = 0.0f;
    if (i < HDIM)        g_gemb[i]   = 0.0f;
    if (i == 0)          g_gcnt[0]   = 0.0f;
}

__global__ void k_deg_init(float* __restrict__ dis, int N) {
    int i = blockIdx.x * blockDim.x + threadIdx.x;
    if (i < N) dis[i] = 1.0f;          // self-loop
}

__global__ void k_deg_count(float* __restrict__ dis, const int* __restrict__ ei, int E) {
    int i = blockIdx.x * blockDim.x + threadIdx.x;
    if (i < E) atomicAdd(&dis[ei[E + i]], 1.0f);   // targets = second row
}

__global__ void k_deg_rsqrt(float* __restrict__ dis, int N) {
    int i = blockIdx.x * blockDim.x + threadIdx.x;
    if (i < N) dis[i] = rsqrtf(dis[i]);            // deg always >0 (self-loops)
}

// ---------------- SGEMM: C[M,256] = A[M,256] @ B[256,256] (fp32) ----------------
// BM=128, BN=128, BK=8, 256 threads, 8x8 micro-tile per thread.
__global__ __launch_bounds__(256) void k_sgemm(const float* __restrict__ A,
                                               const float* __restrict__ B,
                                               float* __restrict__ C, int M) {
    __shared__ float As[8][128];
    __shared__ float Bs[8][128];
    const int t    = threadIdx.x;
    const int row0 = blockIdx.x * 128;
    const int col0 = blockIdx.y * 128;
    const int ty = t >> 4, tx = t & 15;

    const int ar = t >> 1;            // 0..127 (A row within tile)
    const int ac = (t & 1) * 4;       // 0 or 4 (A col within BK)
    const int bk = t >> 5;            // 0..7   (B row within BK)
    const int bj = (t & 31) * 4;      // 0..124 (B col within tile)

    float acc[8][8];
#pragma unroll
    for (int i = 0; i < 8; i++)
#pragma unroll
        for (int j = 0; j < 8; j++) acc[i][j] = 0.0f;

    for (int k0 = 0; k0 < HDIM; k0 += 8) {
        float4 a = *(const float4*)(A + (size_t)(row0 + ar) * HDIM + k0 + ac);
        As[ac + 0][ar] = a.x;
        As[ac + 1][ar] = a.y;
        As[ac + 2][ar] = a.z;
        As[ac + 3][ar] = a.w;
        *(float4*)&Bs[bk][bj] = *(const float4*)(B + (size_t)(k0 + bk) * HDIM + col0 + bj);
        __syncthreads();
#pragma unroll
        for (int k = 0; k < 8; k++) {
            float ra[8], rb[8];
#pragma unroll
            for (int i = 0; i < 8; i++) ra[i] = As[k][ty * 8 + i];
#pragma unroll
            for (int j = 0; j < 8; j++) rb[j] = Bs[k][tx * 8 + j];
#pragma unroll
            for (int i = 0; i < 8; i++)
#pragma unroll
                for (int j = 0; j < 8; j++) acc[i][j] = fmaf(ra[i], rb[j], acc[i][j]);
        }
        __syncthreads();
    }
#pragma unroll
    for (int i = 0; i < 8; i++) {
        float* cp = C + (size_t)(row0 + ty * 8 + i) * HDIM + col0 + tx * 8;
        *(float4*)cp       = make_float4(acc[i][0], acc[i][1], acc[i][2], acc[i][3]);
        *(float4*)(cp + 4) = make_float4(acc[i][4], acc[i][5], acc[i][6], acc[i][7]);
    }
}

// ---------------- self-loop init: agg[i,:] = h[i,:] * dis[i]^2 ----------------
__global__ void k_selfloop(float* __restrict__ agg, const float* __restrict__ h,
                           const float* __restrict__ dis, int N) {
    int idx = blockIdx.x * blockDim.x + threadIdx.x;   // float4 units
    if (idx >= N * 64) return;
    int node = idx >> 6;
    float d  = dis[node];
    float nm = d * d;
    float4 v = ((const float4*)h)[idx];
    v.x *= nm; v.y *= nm; v.z *= nm; v.w *= nm;
    ((float4*)agg)[idx] = v;
}

// ---------------- edge scatter: agg[col] += h[row] * dis[row]*dis[col] ----------------
// 4 edges per block of 256 threads; 64 lanes x float4 per edge.
__global__ void k_scatter(float* __restrict__ agg, const float* __restrict__ h,
                          const float* __restrict__ dis, const int* __restrict__ ei, int E) {
    int e = blockIdx.x * 4 + (threadIdx.x >> 6);
    if (e >= E) return;
    int c = threadIdx.x & 63;
    int r  = ei[e];
    int tg = ei[E + e];
    float nm = dis[r] * dis[tg];
    float4 v = ((const float4*)h)[r * 64 + c];
    float* d = agg + (size_t)tg * HDIM + c * 4;
    atomicAdd(d + 0, v.x * nm);
    atomicAdd(d + 1, v.y * nm);
    atomicAdd(d + 2, v.z * nm);
    atomicAdd(d + 3, v.w * nm);
}

// ---------------- sub pooling: pooled[batch[i]] += relu(agg[i]+b) ; cnt ----------------
__global__ void k_cnt_sub(const int* __restrict__ batch, int N) {
    int i = blockIdx.x * blockDim.x + threadIdx.x;
    if (i < N) atomicAdd(&g_cnt[batch[i]], 1.0f);
}

__global__ void k_pool_sum(const float* __restrict__ agg, const float* __restrict__ b,
                           const int* __restrict__ batch, int N) {
    int idx = blockIdx.x * blockDim.x + threadIdx.x;   // float4 units
    if (idx >= N * 64) return;
    int node = idx >> 6, c = idx & 63;
    int s = batch[node];
    float4 v  = ((const float4*)agg)[idx];
    float4 bb = ((const float4*)b)[c];
    float* d = g_pooled + (size_t)s * HDIM + c * 4;
    atomicAdd(d + 0, fmaxf(v.x + bb.x, 0.0f));
    atomicAdd(d + 1, fmaxf(v.y + bb.y, 0.0f));
    atomicAdd(d + 2, fmaxf(v.z + bb.z, 0.0f));
    atomicAdd(d + 3, fmaxf(v.w + bb.w, 0.0f));
}

__global__ void k_pool_div() {
    int idx = blockIdx.x * blockDim.x + threadIdx.x;
    if (idx >= SSEG * HDIM) return;
    int s = idx >> 8;
    g_pooled[idx] /= fmaxf(g_cnt[s], 1.0f);
}

// ---------------- inject: h_glob[sub_index[s]] += p2[s]  (linearity trick) -------------
__global__ void k_inject(const int* __restrict__ sub_index) {
    int idx = blockIdx.x * blockDim.x + threadIdx.x;   // float4 units over SSEG*64
    if (idx >= SSEG * 64) return;
    int s = idx >> 6, c = idx & 63;
    int node = sub_index[s];
    float4 v = ((const float4*)g_p2)[idx];
    float* d = g_h_glob + (size_t)node * HDIM + c * 4;
    atomicAdd(d + 0, v.x);
    atomicAdd(d + 1, v.y);
    atomicAdd(d + 2, v.z);
    atomicAdd(d + 3, v.w);
}

// ---------------- global pool: gemb += relu(agg_glob + b_glob), cnt ----------------
__global__ void k_gpool(const float* __restrict__ b, const int* __restrict__ batch, int N) {
    int h = threadIdx.x;                 // 256
    int base = blockIdx.x * 64;
    float bb = b[h];
    float acc = 0.0f;
    int cloc = 0;
#pragma unroll 4
    for (int i = 0; i < 64; i++) {
        int node = base + i;
        if (node < N && batch[node] == 0) {
            acc += fmaxf(g_agg_glob[(size_t)node * HDIM + h] + bb, 0.0f);
            cloc++;
        }
    }
    atomicAdd(&g_gemb[h], acc);
    if (h == 0) atomicAdd(&g_gcnt[0], (float)cloc);
}

// ---------------- final: out = (gemb/cnt) @ fc_W^T + fc_b ----------------
__global__ void k_final(const float* __restrict__ fc_W, const float* __restrict__ fc_b,
                        float* __restrict__ out) {
    __shared__ float sg[HDIM];
    int t = threadIdx.x;
    sg[t] = g_gemb[t] / fmaxf(g_gcnt[0], 1.0f);
    __syncthreads();
    float acc = fc_b[t];
    const float* wr = fc_W + (size_t)t * HDIM;
#pragma unroll 8
    for (int h = 0; h < HDIM; h++) acc = fmaf(sg[h], wr[h], acc);
    out[t] = acc;
}

// ---------------- host launcher ----------------
static float* P(const void* sym) { void* p = nullptr; cudaGetSymbolAddress(&p, sym); return (float*)p; }

extern "C" void kernel_launch(void* const* d_in, const int* in_sizes, int n_in,
                              void* d_out, int out_size) {
    const float* x_sub      = (const float*)d_in[0];
    const int*   ei_sub     = (const int*)  d_in[1];
    const int*   batch_sub  = (const int*)  d_in[2];
    const int*   sub_index  = (const int*)  d_in[3];
    const float* x_glob     = (const float*)d_in[4];
    const int*   ei_glob    = (const int*)  d_in[5];
    const int*   batch_glob = (const int*)  d_in[6];
    const float* W_sub      = (const float*)d_in[7];
    const float* b_sub      = (const float*)d_in[8];
    const float* W_glob     = (const float*)d_in[9];
    const float* b_glob     = (const float*)d_in[10];
    const float* fc_W       = (const float*)d_in[11];
    const float* fc_b       = (const float*)d_in[12];
    float* out = (float*)d_out;

    const int E_sub  = in_sizes[1] / 2;
    const int E_glob = in_sizes[5] / 2;

    static float *p_h_sub = nullptr, *p_agg_sub, *p_dis_sub, *p_h_glob, *p_agg_glob,
                 *p_dis_glob, *p_pooled, *p_p2;
    if (!p_h_sub) {
        cudaGetSymbolAddress((void**)&p_h_sub,    g_h_sub);
        cudaGetSymbolAddress((void**)&p_agg_sub,  g_agg_sub);
        cudaGetSymbolAddress((void**)&p_dis_sub,  g_dis_sub);
        cudaGetSymbolAddress((void**)&p_h_glob,   g_h_glob);
        cudaGetSymbolAddress((void**)&p_agg_glob, g_agg_glob);
        cudaGetSymbolAddress((void**)&p_dis_glob, g_dis_glob);
        cudaGetSymbolAddress((void**)&p_pooled,   g_pooled);
        cudaGetSymbolAddress((void**)&p_p2,       g_p2);
    }

    // zero accumulators
    k_zero_misc<<<(SSEG * HDIM + 255) / 256, 256>>>();

    // ---- sub conv ----
    k_deg_init <<<(NSUB + 255) / 256, 256>>>(p_dis_sub, NSUB);
    k_deg_count<<<(E_sub + 255) / 256, 256>>>(p_dis_sub, ei_sub, E_sub);
    k_deg_rsqrt<<<(NSUB + 255) / 256, 256>>>(p_dis_sub, NSUB);

    k_sgemm<<<dim3(NSUB / 128, HDIM / 128), 256>>>(x_sub, W_sub, p_h_sub, NSUB);

    k_selfloop<<<(NSUB * 64 + 255) / 256, 256>>>(p_agg_sub, p_h_sub, p_dis_sub, NSUB);
    k_scatter <<<(E_sub + 3) / 4, 256>>>(p_agg_sub, p_h_sub, p_dis_sub, ei_sub, E_sub);

    k_cnt_sub <<<(NSUB + 255) / 256, 256>>>(batch_sub, NSUB);
    k_pool_sum<<<(NSUB * 64 + 255) / 256, 256>>>(p_agg_sub, b_sub, batch_sub, NSUB);
    k_pool_div<<<(SSEG * HDIM + 255) / 256, 256>>>();

    // ---- glob conv (gx @ W split: x_glob@W + scatter(pooled@W)) ----
    k_deg_init <<<(NGLOB + 255) / 256, 256>>>(p_dis_glob, NGLOB);
    k_deg_count<<<(E_glob + 255) / 256, 256>>>(p_dis_glob, ei_glob, E_glob);
    k_deg_rsqrt<<<(NGLOB + 255) / 256, 256>>>(p_dis_glob, NGLOB);

    k_sgemm<<<dim3(NGLOB / 128, HDIM / 128), 256>>>(x_glob, W_glob, p_h_glob, NGLOB);
    k_sgemm<<<dim3(SSEG / 128, HDIM / 128), 256>>>(p_pooled, W_glob, p_p2, SSEG);
    k_inject<<<(SSEG * 64 + 255) / 256, 256>>>(sub_index);

    k_selfloop<<<(NGLOB * 64 + 255) / 256, 256>>>(p_agg_glob, p_h_glob, p_dis_glob, NGLOB);
    k_scatter <<<(E_glob + 3) / 4, 256>>>(p_agg_glob, p_h_glob, p_dis_glob, ei_glob, E_glob);

    // ---- global mean pool + FC ----
    k_gpool<<<NGLOB / 64, 256>>>(b_glob, batch_glob, NGLOB);
    k_final<<<1, 256>>>(fc_W, fc_b, out);
}

// round 3
// speedup vs baseline: 2.3941x; 2.3941x over previous
#include <cuda_runtime.h>
#include <cuda_bf16.h>
#include <cstdint>

#define HDIM   256
#define NSUB   32768
#define NGLOB  65536
#define SSEG   1024

// ---------------- scratch (device globals; no allocation allowed) ----------------
__device__ float g_h_sub[NSUB * HDIM];
__device__ float g_agg_sub[NSUB * HDIM];
__device__ float g_dis_sub[NSUB];
__device__ float g_pooled[SSEG * HDIM];
__device__ float g_cnt[SSEG];
__device__ float g_h_glob[NGLOB * HDIM];
__device__ float g_agg_glob[NGLOB * HDIM];
__device__ float g_dis_glob[NGLOB];
__device__ float g_p2[SSEG * HDIM];
__device__ float g_gemb[HDIM];
__device__ float g_gcnt[1];

// bf16 packed operands
__device__ __align__(16) __nv_bfloat16 g_bA_sub [NSUB  * HDIM];
__device__ __align__(16) __nv_bfloat16 g_bA_glob[NGLOB * HDIM];
__device__ __align__(16) __nv_bfloat16 g_bA_pool[SSEG  * HDIM];
__device__ __align__(16) __nv_bfloat16 g_bWt_sub [HDIM * HDIM];   // [n][k] = W[k][n]
__device__ __align__(16) __nv_bfloat16 g_bWt_glob[HDIM * HDIM];

// ---------------- PTX helpers ----------------
__device__ __forceinline__ void red4(float* p, float x, float y, float z, float w) {
    asm volatile("red.global.add.v4.f32 [%0], {%1, %2, %3, %4};"
                 :: "l"(p), "f"(x), "f"(y), "f"(z), "f"(w) : "memory");
}
__device__ __forceinline__ void cp_async16(uint32_t dst, const void* src) {
    asm volatile("cp.async.cg.shared.global [%0], [%1], 16;" :: "r"(dst), "l"(src) : "memory");
}
__device__ __forceinline__ void cp_commit() {
    asm volatile("cp.async.commit_group;" ::: "memory");
}
template <int N>
__device__ __forceinline__ void cp_wait() {
    asm volatile("cp.async.wait_group %0;" :: "n"(N) : "memory");
}
__device__ __forceinline__ void ldsm_x4(uint32_t& r0, uint32_t& r1, uint32_t& r2, uint32_t& r3,
                                        uint32_t addr) {
    asm volatile("ldmatrix.sync.aligned.m8n8.x4.shared.b16 {%0,%1,%2,%3}, [%4];"
                 : "=r"(r0), "=r"(r1), "=r"(r2), "=r"(r3) : "r"(addr));
}
__device__ __forceinline__ void mma_bf16(float* c, const uint32_t* a, const uint32_t* b) {
    asm volatile(
        "mma.sync.aligned.m16n8k16.row.col.f32.bf16.bf16.f32 "
        "{%0,%1,%2,%3}, {%4,%5,%6,%7}, {%8,%9}, {%0,%1,%2,%3};"
        : "+f"(c[0]), "+f"(c[1]), "+f"(c[2]), "+f"(c[3])
        : "r"(a[0]), "r"(a[1]), "r"(a[2]), "r"(a[3]), "r"(b[0]), "r"(b[1]));
}

// ---------------- tiny utility kernels ----------------
__global__ void k_zero_misc() {
    int i = blockIdx.x * blockDim.x + threadIdx.x;
    if (i < SSEG * HDIM) g_pooled[i] = 0.0f;
    if (i < SSEG)        g_cnt[i]    = 0.0f;
    if (i < HDIM)        g_gemb[i]   = 0.0f;
    if (i == 0)          g_gcnt[0]   = 0.0f;
}
__global__ void k_deg_init(float* __restrict__ dis, int N) {
    int i = blockIdx.x * blockDim.x + threadIdx.x;
    if (i < N) dis[i] = 1.0f;
}
__global__ void k_deg_count(float* __restrict__ dis, const int* __restrict__ ei, int E) {
    int i = blockIdx.x * blockDim.x + threadIdx.x;
    if (i < E) atomicAdd(&dis[ei[E + i]], 1.0f);
}
__global__ void k_deg_rsqrt(float* __restrict__ dis, int N) {
    int i = blockIdx.x * blockDim.x + threadIdx.x;
    if (i < N) dis[i] = rsqrtf(dis[i]);
}

// ---------------- pack kernels ----------------
__global__ void k_pack_A(const float* __restrict__ A, __nv_bfloat16* __restrict__ out, int M) {
    int vid = blockIdx.x * blockDim.x + threadIdx.x;   // float4 units
    if (vid >= M * 64) return;
    float4 v = ((const float4*)A)[vid];
    __nv_bfloat162 lo = __floats2bfloat162_rn(v.x, v.y);
    __nv_bfloat162 hi = __floats2bfloat162_rn(v.z, v.w);
    uint2 u = make_uint2(*reinterpret_cast<uint32_t*>(&lo), *reinterpret_cast<uint32_t*>(&hi));
    ((uint2*)out)[vid] = u;
}
// Wt[n][k] = W[k][n]
__global__ void k_pack_Wt(const float* __restrict__ W, __nv_bfloat16* __restrict__ out) {
    __shared__ float tile[32][33];
    int bx = blockIdx.x * 32, by = blockIdx.y * 32;
    int tx = threadIdx.x & 31, ty = threadIdx.x >> 5;   // 256 threads: 32x8
    for (int i = 0; i < 32; i += 8)
        tile[ty + i][tx] = W[(by + ty + i) * HDIM + bx + tx];   // W[k][n], k=by.., n=bx..
    __syncthreads();
    for (int i = 0; i < 32; i += 8)
        out[(bx + ty + i) * HDIM + by + tx] = __float2bfloat16(tile[tx][ty + i]);
}

// ---------------- bf16 mma.sync GEMM ----------------
// C[M,256] = A[M,256] @ Wt^T  (Wt is [n][k]); optional fused agg = C * dis^2
// CTA 128x128, BK=64, 2-stage cp.async pipeline. 8 warps -> each 32x64.
#define GEMM_SMEM (4 * 16384)
__global__ __launch_bounds__(256, 2) void k_gemm_mma(
    const __nv_bfloat16* __restrict__ A,
    const __nv_bfloat16* __restrict__ Wt,
    float* __restrict__ Ch,
    float* __restrict__ Cagg,
    const float* __restrict__ dis)
{
    extern __shared__ __align__(16) unsigned char smem[];
    // stage s: A at s*16384, B at 32768 + s*16384. rows of 64 bf16 = 128B = 8 chunks.
    const int tid  = threadIdx.x;
    const int lane = tid & 31, warp = tid >> 5;
    const int wm = warp & 3, wn = warp >> 2;
    const int row0 = blockIdx.x * 128, col0 = blockIdx.y * 128;

    uint32_t sbase = (uint32_t)__cvta_generic_to_shared(smem);

    float acc[2][8][4];
#pragma unroll
    for (int mt = 0; mt < 2; mt++)
#pragma unroll
        for (int nt = 0; nt < 8; nt++)
#pragma unroll
            for (int i = 0; i < 4; i++) acc[mt][nt][i] = 0.0f;

    // loader indices: 1024 16B-chunks per operand-stage, 4 per thread
    const int lr = tid >> 1;              // rows handled: lr, lr+... pattern below
    // simpler: linear chunk id = tid + i*256; r = id>>3, c = id&7
    auto load_stage = [&](int s, int kc) {
        const __nv_bfloat16* Ag = A  + (size_t)(row0)*HDIM + kc * 64;
        const __nv_bfloat16* Bg = Wt + (size_t)(col0)*HDIM + kc * 64;
        uint32_t sA = sbase + s * 16384;
        uint32_t sB = sbase + 32768 + s * 16384;
#pragma unroll
        for (int i = 0; i < 4; i++) {
            int id = tid + i * 256;
            int r = id >> 3, c = id & 7;
            uint32_t d = (uint32_t)(r * 128 + ((c ^ (r & 7)) << 4));
            cp_async16(sA + d, Ag + (size_t)r * HDIM + c * 8);
            cp_async16(sB + d, Bg + (size_t)r * HDIM + c * 8);
        }
        cp_commit();
    };

    load_stage(0, 0);
    int s = 0;
#pragma unroll 1
    for (int kc = 0; kc < 4; kc++) {
        if (kc < 3) load_stage(s ^ 1, kc + 1);
        if (kc < 3) cp_wait<1>(); else cp_wait<0>();
        __syncthreads();

        uint32_t sA = sbase + s * 16384;
        uint32_t sB = sbase + 32768 + s * 16384;
#pragma unroll
        for (int kk = 0; kk < 4; kk++) {
            uint32_t af[2][4];
#pragma unroll
            for (int mt = 0; mt < 2; mt++) {
                int r = wm * 32 + mt * 16 + (lane & 15);
                int c = kk * 2 + (lane >> 4);
                uint32_t addr = sA + r * 128 + ((c ^ (r & 7)) << 4);
                ldsm_x4(af[mt][0], af[mt][1], af[mt][2], af[mt][3], addr);
            }
            uint32_t bf[8][2];
#pragma unroll
            for (int p = 0; p < 4; p++) {
                int r = wn * 64 + p * 16 + ((lane >> 4) << 3) + (lane & 7);
                int c = kk * 2 + ((lane >> 3) & 1);
                uint32_t addr = sB + r * 128 + ((c ^ (r & 7)) << 4);
                ldsm_x4(bf[2 * p][0], bf[2 * p][1], bf[2 * p + 1][0], bf[2 * p + 1][1], addr);
            }
#pragma unroll
            for (int mt = 0; mt < 2; mt++)
#pragma unroll
                for (int nt = 0; nt < 8; nt++)
                    mma_bf16(acc[mt][nt], af[mt], bf[nt]);
        }
        __syncthreads();
        s ^= 1;
    }

    // epilogue
    const int g = lane >> 2, t = lane & 3;
#pragma unroll
    for (int mt = 0; mt < 2; mt++) {
        int r_lo = row0 + wm * 32 + mt * 16 + g;
        int r_hi = r_lo + 8;
        float d2lo = 0.0f, d2hi = 0.0f;
        if (dis) {
            float a = dis[r_lo], b = dis[r_hi];
            d2lo = a * a; d2hi = b * b;
        }
#pragma unroll
        for (int nt = 0; nt < 8; nt++) {
            int col = col0 + wn * 64 + nt * 8 + 2 * t;
            float2 lo = make_float2(acc[mt][nt][0], acc[mt][nt][1]);
            float2 hi = make_float2(acc[mt][nt][2], acc[mt][nt][3]);
            *(float2*)&Ch[(size_t)r_lo * HDIM + col] = lo;
            *(float2*)&Ch[(size_t)r_hi * HDIM + col] = hi;
            if (Cagg) {
                *(float2*)&Cagg[(size_t)r_lo * HDIM + col] = make_float2(lo.x * d2lo, lo.y * d2lo);
                *(float2*)&Cagg[(size_t)r_hi * HDIM + col] = make_float2(hi.x * d2hi, hi.y * d2hi);
            }
        }
    }
}

// ---------------- edge scatter: agg[col] += h[row] * dis[row]*dis[col] ----------------
__global__ void k_scatter(float* __restrict__ agg, const float* __restrict__ h,
                          const float* __restrict__ dis, const int* __restrict__ ei, int E) {
    int e = blockIdx.x * 4 + (threadIdx.x >> 6);
    if (e >= E) return;
    int c  = threadIdx.x & 63;
    int r  = ei[e];
    int tg = ei[E + e];
    float nm = dis[r] * dis[tg];
    float4 v = ((const float4*)h)[r * 64 + c];
    red4(agg + (size_t)tg * HDIM + c * 4, v.x * nm, v.y * nm, v.z * nm, v.w * nm);
}

// ---------------- sub pooling ----------------
__global__ void k_cnt_sub(const int* __restrict__ batch, int N) {
    int i = blockIdx.x * blockDim.x + threadIdx.x;
    if (i < N) atomicAdd(&g_cnt[batch[i]], 1.0f);
}
__global__ void k_pool_sum(const float* __restrict__ agg, const float* __restrict__ b,
                           const int* __restrict__ batch, int N) {
    int idx = blockIdx.x * blockDim.x + threadIdx.x;   // float4 units
    if (idx >= N * 64) return;
    int node = idx >> 6, c = idx & 63;
    int s = batch[node];
    float4 v  = ((const float4*)agg)[idx];
    float4 bb = ((const float4*)b)[c];
    red4(g_pooled + (size_t)s * HDIM + c * 4,
         fmaxf(v.x + bb.x, 0.0f), fmaxf(v.y + bb.y, 0.0f),
         fmaxf(v.z + bb.z, 0.0f), fmaxf(v.w + bb.w, 0.0f));
}
__global__ void k_pool_div() {
    int idx = blockIdx.x * blockDim.x + threadIdx.x;
    if (idx >= SSEG * HDIM) return;
    int s = idx >> 8;
    g_pooled[idx] /= fmaxf(g_cnt[s], 1.0f);
}

// ---------------- inject: h_glob[n] += p2[s]; agg_glob[n] += p2[s]*dis[n]^2 ----------
__global__ void k_inject(const int* __restrict__ sub_index) {
    int idx = blockIdx.x * blockDim.x + threadIdx.x;   // float4 units over SSEG*64
    if (idx >= SSEG * 64) return;
    int s = idx >> 6, c = idx & 63;
    int node = sub_index[s];
    float d  = g_dis_glob[node];
    float d2 = d * d;
    float4 v = ((const float4*)g_p2)[idx];
    red4(g_h_glob   + (size_t)node * HDIM + c * 4, v.x, v.y, v.z, v.w);
    red4(g_agg_glob + (size_t)node * HDIM + c * 4, v.x * d2, v.y * d2, v.z * d2, v.w * d2);
}

// ---------------- global pool ----------------
__global__ void k_gpool(const float* __restrict__ b, const int* __restrict__ batch, int N) {
    int h = threadIdx.x;
    int base = blockIdx.x * 64;
    float bb = b[h];
    float acc = 0.0f;
    int cloc = 0;
#pragma unroll 4
    for (int i = 0; i < 64; i++) {
        int node = base + i;
        if (node < N && batch[node] == 0) {
            acc += fmaxf(g_agg_glob[(size_t)node * HDIM + h] + bb, 0.0f);
            cloc++;
        }
    }
    atomicAdd(&g_gemb[h], acc);
    if (h == 0) atomicAdd(&g_gcnt[0], (float)cloc);
}

// ---------------- final: out = (gemb/cnt) @ fc_W^T + fc_b ----------------
__global__ void k_final(const float* __restrict__ fc_W, const float* __restrict__ fc_b,
                        float* __restrict__ out) {
    __shared__ float sg[HDIM];
    int t = threadIdx.x;
    sg[t] = g_gemb[t] / fmaxf(g_gcnt[0], 1.0f);
    __syncthreads();
    float acc = fc_b[t];
    const float* wr = fc_W + (size_t)t * HDIM;
#pragma unroll 8
    for (int h = 0; h < HDIM; h++) acc = fmaf(sg[h], wr[h], acc);
    out[t] = acc;
}

// ---------------- host launcher ----------------
extern "C" void kernel_launch(void* const* d_in, const int* in_sizes, int n_in,
                              void* d_out, int out_size) {
    const float* x_sub      = (const float*)d_in[0];
    const int*   ei_sub     = (const int*)  d_in[1];
    const int*   batch_sub  = (const int*)  d_in[2];
    const int*   sub_index  = (const int*)  d_in[3];
    const float* x_glob     = (const float*)d_in[4];
    const int*   ei_glob    = (const int*)  d_in[5];
    const int*   batch_glob = (const int*)  d_in[6];
    const float* W_sub      = (const float*)d_in[7];
    const float* b_sub      = (const float*)d_in[8];
    const float* W_glob     = (const float*)d_in[9];
    const float* b_glob     = (const float*)d_in[10];
    const float* fc_W       = (const float*)d_in[11];
    const float* fc_b       = (const float*)d_in[12];
    float* out = (float*)d_out;

    const int E_sub  = in_sizes[1] / 2;
    const int E_glob = in_sizes[5] / 2;

    static float *p_h_sub = nullptr, *p_agg_sub, *p_dis_sub, *p_h_glob, *p_agg_glob,
                 *p_dis_glob, *p_pooled, *p_p2;
    static __nv_bfloat16 *pb_a_sub, *pb_a_glob, *pb_a_pool, *pb_wt_sub, *pb_wt_glob;
    if (!p_h_sub) {
        cudaGetSymbolAddress((void**)&p_h_sub,    g_h_sub);
        cudaGetSymbolAddress((void**)&p_agg_sub,  g_agg_sub);
        cudaGetSymbolAddress((void**)&p_dis_sub,  g_dis_sub);
        cudaGetSymbolAddress((void**)&p_h_glob,   g_h_glob);
        cudaGetSymbolAddress((void**)&p_agg_glob, g_agg_glob);
        cudaGetSymbolAddress((void**)&p_dis_glob, g_dis_glob);
        cudaGetSymbolAddress((void**)&p_pooled,   g_pooled);
        cudaGetSymbolAddress((void**)&p_p2,       g_p2);
        cudaGetSymbolAddress((void**)&pb_a_sub,   g_bA_sub);
        cudaGetSymbolAddress((void**)&pb_a_glob,  g_bA_glob);
        cudaGetSymbolAddress((void**)&pb_a_pool,  g_bA_pool);
        cudaGetSymbolAddress((void**)&pb_wt_sub,  g_bWt_sub);
        cudaGetSymbolAddress((void**)&pb_wt_glob, g_bWt_glob);
        cudaFuncSetAttribute(k_gemm_mma, cudaFuncAttributeMaxDynamicSharedMemorySize, GEMM_SMEM);
    }

    k_zero_misc<<<(SSEG * HDIM + 255) / 256, 256>>>();

    // ---- sub conv ----
    k_deg_init <<<(NSUB + 255) / 256, 256>>>(p_dis_sub, NSUB);
    k_deg_count<<<(E_sub + 255) / 256, 256>>>(p_dis_sub, ei_sub, E_sub);
    k_deg_rsqrt<<<(NSUB + 255) / 256, 256>>>(p_dis_sub, NSUB);

    k_pack_Wt<<<dim3(8, 8), 256>>>(W_sub, pb_wt_sub);
    k_pack_A <<<(NSUB * 64 + 255) / 256, 256>>>(x_sub, pb_a_sub, NSUB);
    k_gemm_mma<<<dim3(NSUB / 128, 2), 256, GEMM_SMEM>>>(pb_a_sub, pb_wt_sub,
                                                        p_h_sub, p_agg_sub, p_dis_sub);

    k_scatter <<<(E_sub + 3) / 4, 256>>>(p_agg_sub, p_h_sub, p_dis_sub, ei_sub, E_sub);

    k_cnt_sub <<<(NSUB + 255) / 256, 256>>>(batch_sub, NSUB);
    k_pool_sum<<<(NSUB * 64 + 255) / 256, 256>>>(p_agg_sub, b_sub, batch_sub, NSUB);
    k_pool_div<<<(SSEG * HDIM + 255) / 256, 256>>>();

    // ---- glob conv (gx @ W split: x_glob@W + scatter(pooled@W)) ----
    k_deg_init <<<(NGLOB + 255) / 256, 256>>>(p_dis_glob, NGLOB);
    k_deg_count<<<(E_glob + 255) / 256, 256>>>(p_dis_glob, ei_glob, E_glob);
    k_deg_rsqrt<<<(NGLOB + 255) / 256, 256>>>(p_dis_glob, NGLOB);

    k_pack_Wt<<<dim3(8, 8), 256>>>(W_glob, pb_wt_glob);
    k_pack_A <<<(NGLOB * 64 + 255) / 256, 256>>>(x_glob, pb_a_glob, NGLOB);
    k_gemm_mma<<<dim3(NGLOB / 128, 2), 256, GEMM_SMEM>>>(pb_a_glob, pb_wt_glob,
                                                         p_h_glob, p_agg_glob, p_dis_glob);

    k_pack_A <<<(SSEG * 64 + 255) / 256, 256>>>(p_pooled, pb_a_pool, SSEG);
    k_gemm_mma<<<dim3(SSEG / 128, 2), 256, GEMM_SMEM>>>(pb_a_pool, pb_wt_glob,
                                                        p_p2, nullptr, nullptr);
    k_inject<<<(SSEG * 64 + 255) / 256, 256>>>(sub_index);

    k_scatter <<<(E_glob + 3) / 4, 256>>>(p_agg_glob, p_h_glob, p_dis_glob, ei_glob, E_glob);

    // ---- global mean pool + FC ----
    k_gpool<<<NGLOB / 64, 256>>>(b_glob, batch_glob, NGLOB);
    k_final<<<1, 256>>>(fc_W, fc_b, out);
}

// round 4
// speedup vs baseline: 2.8370x; 1.1850x over previous
#include <cuda_runtime.h>
#include <cuda_bf16.h>
#include <cstdint>

#define HDIM   256
#define NSUB   32768
#define NGLOB  65536
#define SSEG   1024
#define ESUB_MAX   262144
#define EGLOB_MAX  1048576
#define CAPS (ESUB_MAX  + 4 * NSUB)    // padded CSR capacity
#define CAPG (EGLOB_MAX + 4 * NGLOB)

// ---------------- scratch (device globals; no allocation allowed) ----------------
__device__ float g_dis_sub[NSUB];
__device__ float g_dis_glob[NGLOB];
__device__ float g_pooled[SSEG * HDIM];
__device__ float g_cnt[SSEG];
__device__ float g_p2[SSEG * HDIM];
__device__ float g_gemb_part[64 * HDIM];
__device__ int   g_gcnt;

__device__ int g_cntdeg_sub[NSUB];
__device__ int g_cntdeg_glob[NGLOB];
__device__ int g_off_sub[NSUB + 1];
__device__ int g_off_glob[NGLOB + 1];
__device__ int g_cur_sub[NSUB];
__device__ int g_cur_glob[NGLOB];
__device__ __align__(16) int g_csr_sub[CAPS];
__device__ __align__(16) int g_csr_glob[CAPG];

// bf16 buffers: hs = (x@W)*dis, with one extra zero row (sentinel)
__device__ __align__(16) __nv_bfloat16 g_hs_sub [(NSUB  + 1) * HDIM];
__device__ __align__(16) __nv_bfloat16 g_hs_glob[(NGLOB + 1) * HDIM];
__device__ __align__(16) __nv_bfloat16 g_bA_sub [NSUB  * HDIM];
__device__ __align__(16) __nv_bfloat16 g_bA_glob[NGLOB * HDIM];
__device__ __align__(16) __nv_bfloat16 g_bA_pool[SSEG  * HDIM];
__device__ __align__(16) __nv_bfloat16 g_bWt_sub [HDIM * HDIM];
__device__ __align__(16) __nv_bfloat16 g_bWt_glob[HDIM * HDIM];

// ---------------- PTX helpers ----------------
__device__ __forceinline__ void red4(float* p, float x, float y, float z, float w) {
    asm volatile("red.global.add.v4.f32 [%0], {%1, %2, %3, %4};"
                 :: "l"(p), "f"(x), "f"(y), "f"(z), "f"(w) : "memory");
}
__device__ __forceinline__ void cp_async16(uint32_t dst, const void* src) {
    asm volatile("cp.async.cg.shared.global [%0], [%1], 16;" :: "r"(dst), "l"(src) : "memory");
}
__device__ __forceinline__ void cp_commit() {
    asm volatile("cp.async.commit_group;" ::: "memory");
}
template <int N>
__device__ __forceinline__ void cp_wait() {
    asm volatile("cp.async.wait_group %0;" :: "n"(N) : "memory");
}
__device__ __forceinline__ void ldsm_x4(uint32_t& r0, uint32_t& r1, uint32_t& r2, uint32_t& r3,
                                        uint32_t addr) {
    asm volatile("ldmatrix.sync.aligned.m8n8.x4.shared.b16 {%0,%1,%2,%3}, [%4];"
                 : "=r"(r0), "=r"(r1), "=r"(r2), "=r"(r3) : "r"(addr));
}
__device__ __forceinline__ void mma_bf16(float* c, const uint32_t* a, const uint32_t* b) {
    asm volatile(
        "mma.sync.aligned.m16n8k16.row.col.f32.bf16.bf16.f32 "
        "{%0,%1,%2,%3}, {%4,%5,%6,%7}, {%8,%9}, {%0,%1,%2,%3};"
        : "+f"(c[0]), "+f"(c[1]), "+f"(c[2]), "+f"(c[3])
        : "r"(a[0]), "r"(a[1]), "r"(a[2]), "r"(a[3]), "r"(b[0]), "r"(b[1]));
}
__device__ __forceinline__ __nv_bfloat162 badd2(__nv_bfloat162 a, __nv_bfloat162 b) {
    return __hadd2(a, b);
}

// ---------------- init kernels ----------------
__global__ void k_zero_misc() {
    int i = blockIdx.x * blockDim.x + threadIdx.x;       // grid covers 262144
    if (i < SSEG * HDIM) g_pooled[i] = 0.0f;
    if (i < 64 * HDIM)   g_gemb_part[i] = 0.0f;
    if (i < SSEG)        g_cnt[i] = 0.0f;
    if (i < NGLOB)       g_cntdeg_glob[i] = 0;
    if (i < NSUB)        g_cntdeg_sub[i]  = 0;
    if (i < HDIM) {
        g_hs_sub [NSUB  * HDIM + i] = __float2bfloat16(0.0f);
        g_hs_glob[NGLOB * HDIM + i] = __float2bfloat16(0.0f);
    }
    if (i == 0) g_gcnt = 0;
}
__global__ void k_prefill_csr() {
    int i = blockIdx.x * blockDim.x + threadIdx.x;       // grid covers CAPG
    if (i < CAPG) g_csr_glob[i] = NGLOB;
    if (i < CAPS) g_csr_sub[i]  = NSUB;
}
__global__ void k_hist(int* __restrict__ cnt, const int* __restrict__ ei, int E) {
    int i = blockIdx.x * blockDim.x + threadIdx.x;
    if (i < E) atomicAdd(&cnt[ei[E + i]], 1);
}
__global__ void k_dis(float* __restrict__ dis, const int* __restrict__ cnt, int N) {
    int i = blockIdx.x * blockDim.x + threadIdx.x;
    if (i < N) dis[i] = rsqrtf((float)cnt[i] + 1.0f);
}
// single-block exclusive scan of padded degrees -> off / cur
__global__ __launch_bounds__(1024) void k_scan(const int* __restrict__ cnt,
                                               int* __restrict__ off,
                                               int* __restrict__ cur, int N) {
    __shared__ int tot[1024];
    int t = threadIdx.x;
    int chunk = N >> 10;
    int base = t * chunk;
    int s = 0;
    for (int i = 0; i < chunk; i++) s += (cnt[base + i] + 3) & ~3;
    tot[t] = s;
    __syncthreads();
    for (int d = 1; d < 1024; d <<= 1) {
        int v = (t >= d) ? tot[t - d] : 0;
        __syncthreads();
        tot[t] += v;
        __syncthreads();
    }
    int run = (t > 0) ? tot[t - 1] : 0;
    for (int i = 0; i < chunk; i++) {
        off[base + i] = run;
        cur[base + i] = run;
        run += (cnt[base + i] + 3) & ~3;
    }
    if (t == 1023) off[N] = run;
}
__global__ void k_fill(int* __restrict__ csr, int* __restrict__ cur,
                       const int* __restrict__ ei, int E) {
    int i = blockIdx.x * blockDim.x + threadIdx.x;
    if (i >= E) return;
    int tgt = ei[E + i];
    int p = atomicAdd(&cur[tgt], 1);
    csr[p] = ei[i];
}

// ---------------- pack kernels ----------------
__global__ void k_pack_A(const float* __restrict__ A, __nv_bfloat16* __restrict__ out, int M) {
    int vid = blockIdx.x * blockDim.x + threadIdx.x;
    if (vid >= M * 64) return;
    float4 v = ((const float4*)A)[vid];
    __nv_bfloat162 lo = __floats2bfloat162_rn(v.x, v.y);
    __nv_bfloat162 hi = __floats2bfloat162_rn(v.z, v.w);
    ((uint2*)out)[vid] = make_uint2(*reinterpret_cast<uint32_t*>(&lo),
                                    *reinterpret_cast<uint32_t*>(&hi));
}
__global__ void k_pack_Wt(const float* __restrict__ W, __nv_bfloat16* __restrict__ out) {
    __shared__ float tile[32][33];
    int bx = blockIdx.x * 32, by = blockIdx.y * 32;
    int tx = threadIdx.x & 31, ty = threadIdx.x >> 5;
    for (int i = 0; i < 32; i += 8)
        tile[ty + i][tx] = W[(by + ty + i) * HDIM + bx + tx];
    __syncthreads();
    for (int i = 0; i < 32; i += 8)
        out[(bx + ty + i) * HDIM + by + tx] = __float2bfloat16(tile[tx][ty + i]);
}

// ---------------- bf16 mma.sync GEMM ----------------
// If dis != null: writes Hs[r][c] = bf16( C[r][c] * dis[r] )   (pre-scaled messages)
// else:           writes Cf fp32.
#define GEMM_SMEM (4 * 16384)
__global__ __launch_bounds__(256, 2) void k_gemm_mma(
    const __nv_bfloat16* __restrict__ A,
    const __nv_bfloat16* __restrict__ Wt,
    __nv_bfloat16* __restrict__ Hs,
    float* __restrict__ Cf,
    const float* __restrict__ dis)
{
    extern __shared__ __align__(16) unsigned char smem[];
    const int tid  = threadIdx.x;
    const int lane = tid & 31, warp = tid >> 5;
    const int wm = warp & 3, wn = warp >> 2;
    const int row0 = blockIdx.x * 128, col0 = blockIdx.y * 128;
    uint32_t sbase = (uint32_t)__cvta_generic_to_shared(smem);

    float acc[2][8][4];
#pragma unroll
    for (int mt = 0; mt < 2; mt++)
#pragma unroll
        for (int nt = 0; nt < 8; nt++)
#pragma unroll
            for (int i = 0; i < 4; i++) acc[mt][nt][i] = 0.0f;

    auto load_stage = [&](int s, int kc) {
        const __nv_bfloat16* Ag = A  + (size_t)(row0)*HDIM + kc * 64;
        const __nv_bfloat16* Bg = Wt + (size_t)(col0)*HDIM + kc * 64;
        uint32_t sA = sbase + s * 16384;
        uint32_t sB = sbase + 32768 + s * 16384;
#pragma unroll
        for (int i = 0; i < 4; i++) {
            int id = tid + i * 256;
            int r = id >> 3, c = id & 7;
            uint32_t d = (uint32_t)(r * 128 + ((c ^ (r & 7)) << 4));
            cp_async16(sA + d, Ag + (size_t)r * HDIM + c * 8);
            cp_async16(sB + d, Bg + (size_t)r * HDIM + c * 8);
        }
        cp_commit();
    };

    load_stage(0, 0);
    int s = 0;
#pragma unroll 1
    for (int kc = 0; kc < 4; kc++) {
        if (kc < 3) load_stage(s ^ 1, kc + 1);
        if (kc < 3) cp_wait<1>(); else cp_wait<0>();
        __syncthreads();
        uint32_t sA = sbase + s * 16384;
        uint32_t sB = sbase + 32768 + s * 16384;
#pragma unroll
        for (int kk = 0; kk < 4; kk++) {
            uint32_t af[2][4];
#pragma unroll
            for (int mt = 0; mt < 2; mt++) {
                int r = wm * 32 + mt * 16 + (lane & 15);
                int c = kk * 2 + (lane >> 4);
                ldsm_x4(af[mt][0], af[mt][1], af[mt][2], af[mt][3],
                        sA + r * 128 + ((c ^ (r & 7)) << 4));
            }
            uint32_t bf[8][2];
#pragma unroll
            for (int p = 0; p < 4; p++) {
                int r = wn * 64 + p * 16 + ((lane >> 4) << 3) + (lane & 7);
                int c = kk * 2 + ((lane >> 3) & 1);
                ldsm_x4(bf[2 * p][0], bf[2 * p][1], bf[2 * p + 1][0], bf[2 * p + 1][1],
                        sB + r * 128 + ((c ^ (r & 7)) << 4));
            }
#pragma unroll
            for (int mt = 0; mt < 2; mt++)
#pragma unroll
                for (int nt = 0; nt < 8; nt++)
                    mma_bf16(acc[mt][nt], af[mt], bf[nt]);
        }
        __syncthreads();
        s ^= 1;
    }

    const int g = lane >> 2, t4 = lane & 3;
#pragma unroll
    for (int mt = 0; mt < 2; mt++) {
        int r_lo = row0 + wm * 32 + mt * 16 + g;
        int r_hi = r_lo + 8;
        if (dis) {
            float dlo = dis[r_lo], dhi = dis[r_hi];
#pragma unroll
            for (int nt = 0; nt < 8; nt++) {
                int col = col0 + wn * 64 + nt * 8 + 2 * t4;
                __nv_bfloat162 lo = __floats2bfloat162_rn(acc[mt][nt][0] * dlo,
                                                          acc[mt][nt][1] * dlo);
                __nv_bfloat162 hi = __floats2bfloat162_rn(acc[mt][nt][2] * dhi,
                                                          acc[mt][nt][3] * dhi);
                *(__nv_bfloat162*)&Hs[(size_t)r_lo * HDIM + col] = lo;
                *(__nv_bfloat162*)&Hs[(size_t)r_hi * HDIM + col] = hi;
            }
        } else {
#pragma unroll
            for (int nt = 0; nt < 8; nt++) {
                int col = col0 + wn * 64 + nt * 8 + 2 * t4;
                *(float2*)&Cf[(size_t)r_lo * HDIM + col] =
                    make_float2(acc[mt][nt][0], acc[mt][nt][1]);
                *(float2*)&Cf[(size_t)r_hi * HDIM + col] =
                    make_float2(acc[mt][nt][2], acc[mt][nt][3]);
            }
        }
    }
}

// ---------------- CSR gather + fused bias/relu/pool ----------------
// 32 threads per node, 8 dims each (bf16x8 = 16B). agg[n] = dis[n]*(hs[n]+sum_in hs[src])
// sub: red4 relu(agg+b) into pooled[batch[n]]
__global__ __launch_bounds__(256) void k_gather_sub(
    const int* __restrict__ batch, const float* __restrict__ bias)
{
    const int lane = threadIdx.x & 31, grp = threadIdx.x >> 5;
    const uint4* H = (const uint4*)g_hs_sub;
    float4 b0 = ((const float4*)bias)[lane * 2];
    float4 b1 = ((const float4*)bias)[lane * 2 + 1];
#pragma unroll 1
    for (int it = 0; it < 4; it++) {
        int n = blockIdx.x * 32 + it * 8 + grp;
        int o0 = g_off_sub[n] >> 2, o1 = g_off_sub[n + 1] >> 2;
        uint4 a = H[(size_t)n * 32 + lane];
        __nv_bfloat162 A0 = *(__nv_bfloat162*)&a.x, A1 = *(__nv_bfloat162*)&a.y,
                       A2 = *(__nv_bfloat162*)&a.z, A3 = *(__nv_bfloat162*)&a.w;
#pragma unroll 1
        for (int k = o0; k < o1; k++) {
            int4 s4 = ((const int4*)g_csr_sub)[k];
            uint4 v;
            v = H[(size_t)s4.x * 32 + lane];
            A0 = badd2(A0, *(__nv_bfloat162*)&v.x); A1 = badd2(A1, *(__nv_bfloat162*)&v.y);
            A2 = badd2(A2, *(__nv_bfloat162*)&v.z); A3 = badd2(A3, *(__nv_bfloat162*)&v.w);
            v = H[(size_t)s4.y * 32 + lane];
            A0 = badd2(A0, *(__nv_bfloat162*)&v.x); A1 = badd2(A1, *(__nv_bfloat162*)&v.y);
            A2 = badd2(A2, *(__nv_bfloat162*)&v.z); A3 = badd2(A3, *(__nv_bfloat162*)&v.w);
            v = H[(size_t)s4.z * 32 + lane];
            A0 = badd2(A0, *(__nv_bfloat162*)&v.x); A1 = badd2(A1, *(__nv_bfloat162*)&v.y);
            A2 = badd2(A2, *(__nv_bfloat162*)&v.z); A3 = badd2(A3, *(__nv_bfloat162*)&v.w);
            v = H[(size_t)s4.w * 32 + lane];
            A0 = badd2(A0, *(__nv_bfloat162*)&v.x); A1 = badd2(A1, *(__nv_bfloat162*)&v.y);
            A2 = badd2(A2, *(__nv_bfloat162*)&v.z); A3 = badd2(A3, *(__nv_bfloat162*)&v.w);
        }
        float d = g_dis_sub[n];
        float2 f0 = __bfloat1622float2(A0), f1 = __bfloat1622float2(A1);
        float2 f2 = __bfloat1622float2(A2), f3 = __bfloat1622float2(A3);
        float* dst = g_pooled + (size_t)batch[n] * HDIM + lane * 8;
        red4(dst,
             fmaxf(fmaf(f0.x, d, b0.x), 0.0f), fmaxf(fmaf(f0.y, d, b0.y), 0.0f),
             fmaxf(fmaf(f1.x, d, b0.z), 0.0f), fmaxf(fmaf(f1.y, d, b0.w), 0.0f));
        red4(dst + 4,
             fmaxf(fmaf(f2.x, d, b1.x), 0.0f), fmaxf(fmaf(f2.y, d, b1.y), 0.0f),
             fmaxf(fmaf(f3.x, d, b1.z), 0.0f), fmaxf(fmaf(f3.y, d, b1.w), 0.0f));
    }
}

// glob: accumulate relu(agg+b) of batch==0 nodes into gemb_part replica; count nodes.
__global__ __launch_bounds__(256) void k_gather_glob(
    const int* __restrict__ batch, const float* __restrict__ bias)
{
    const int lane = threadIdx.x & 31, grp = threadIdx.x >> 5;
    const uint4* H = (const uint4*)g_hs_glob;
    float4 b0 = ((const float4*)bias)[lane * 2];
    float4 b1 = ((const float4*)bias)[lane * 2 + 1];
    float r0 = 0, r1 = 0, r2 = 0, r3 = 0, r4 = 0, r5 = 0, r6 = 0, r7 = 0;
    int cloc = 0;
#pragma unroll 1
    for (int it = 0; it < 4; it++) {
        int n = blockIdx.x * 32 + it * 8 + grp;
        int o0 = g_off_glob[n] >> 2, o1 = g_off_glob[n + 1] >> 2;
        uint4 a = H[(size_t)n * 32 + lane];
        __nv_bfloat162 A0 = *(__nv_bfloat162*)&a.x, A1 = *(__nv_bfloat162*)&a.y,
                       A2 = *(__nv_bfloat162*)&a.z, A3 = *(__nv_bfloat162*)&a.w;
#pragma unroll 1
        for (int k = o0; k < o1; k++) {
            int4 s4 = ((const int4*)g_csr_glob)[k];
            uint4 v;
            v = H[(size_t)s4.x * 32 + lane];
            A0 = badd2(A0, *(__nv_bfloat162*)&v.x); A1 = badd2(A1, *(__nv_bfloat162*)&v.y);
            A2 = badd2(A2, *(__nv_bfloat162*)&v.z); A3 = badd2(A3, *(__nv_bfloat162*)&v.w);
            v = H[(size_t)s4.y * 32 + lane];
            A0 = badd2(A0, *(__nv_bfloat162*)&v.x); A1 = badd2(A1, *(__nv_bfloat162*)&v.y);
            A2 = badd2(A2, *(__nv_bfloat162*)&v.z); A3 = badd2(A3, *(__nv_bfloat162*)&v.w);
            v = H[(size_t)s4.z * 32 + lane];
            A0 = badd2(A0, *(__nv_bfloat162*)&v.x); A1 = badd2(A1, *(__nv_bfloat162*)&v.y);
            A2 = badd2(A2, *(__nv_bfloat162*)&v.z); A3 = badd2(A3, *(__nv_bfloat162*)&v.w);
            v = H[(size_t)s4.w * 32 + lane];
            A0 = badd2(A0, *(__nv_bfloat162*)&v.x); A1 = badd2(A1, *(__nv_bfloat162*)&v.y);
            A2 = badd2(A2, *(__nv_bfloat162*)&v.z); A3 = badd2(A3, *(__nv_bfloat162*)&v.w);
        }
        if (batch[n] == 0) {
            float d = g_dis_glob[n];
            float2 f0 = __bfloat1622float2(A0), f1 = __bfloat1622float2(A1);
            float2 f2 = __bfloat1622float2(A2), f3 = __bfloat1622float2(A3);
            r0 += fmaxf(fmaf(f0.x, d, b0.x), 0.0f);
            r1 += fmaxf(fmaf(f0.y, d, b0.y), 0.0f);
            r2 += fmaxf(fmaf(f1.x, d, b0.z), 0.0f);
            r3 += fmaxf(fmaf(f1.y, d, b0.w), 0.0f);
            r4 += fmaxf(fmaf(f2.x, d, b1.x), 0.0f);
            r5 += fmaxf(fmaf(f2.y, d, b1.y), 0.0f);
            r6 += fmaxf(fmaf(f3.x, d, b1.z), 0.0f);
            r7 += fmaxf(fmaf(f3.y, d, b1.w), 0.0f);
            cloc++;
        }
    }
    float* dst = g_gemb_part + (size_t)(blockIdx.x & 63) * HDIM + lane * 8;
    red4(dst, r0, r1, r2, r3);
    red4(dst + 4, r4, r5, r6, r7);
    if (lane == 0) atomicAdd(&g_gcnt, cloc);
}

// ---------------- pooling finalize / inject / final ----------------
__global__ void k_cnt_sub(const int* __restrict__ batch, int N) {
    int i = blockIdx.x * blockDim.x + threadIdx.x;
    if (i < N) atomicAdd(&g_cnt[batch[i]], 1.0f);
}
__global__ void k_pool_div() {
    int idx = blockIdx.x * blockDim.x + threadIdx.x;
    if (idx >= SSEG * HDIM) return;
    int s = idx >> 8;
    g_pooled[idx] /= fmaxf(g_cnt[s], 1.0f);
}
// hs_glob[node] += bf16( p2[s] * dis[node] )   (unique nodes: plain rmw)
__global__ void k_inject(const int* __restrict__ sub_index) {
    int idx = blockIdx.x * blockDim.x + threadIdx.x;   // bf16x2 units over SSEG*128
    if (idx >= SSEG * 128) return;
    int s = idx >> 7, c2 = idx & 127;
    int node = sub_index[s];
    float d = g_dis_glob[node];
    __nv_bfloat162* hp = (__nv_bfloat162*)g_hs_glob + (size_t)node * 128 + c2;
    float2 h = __bfloat1622float2(*hp);
    const float* p = g_p2 + (size_t)s * HDIM + c2 * 2;
    *hp = __floats2bfloat162_rn(fmaf(p[0], d, h.x), fmaf(p[1], d, h.y));
}
__global__ void k_final(const float* __restrict__ fc_W, const float* __restrict__ fc_b,
                        float* __restrict__ out) {
    __shared__ float sg[HDIM];
    int t = threadIdx.x;
    float s = 0.0f;
#pragma unroll 8
    for (int p = 0; p < 64; p++) s += g_gemb_part[p * HDIM + t];
    sg[t] = s / fmaxf((float)g_gcnt, 1.0f);
    __syncthreads();
    float acc = fc_b[t];
    const float* wr = fc_W + (size_t)t * HDIM;
#pragma unroll 8
    for (int h = 0; h < HDIM; h++) acc = fmaf(sg[h], wr[h], acc);
    out[t] = acc;
}

// ---------------- host launcher ----------------
extern "C" void kernel_launch(void* const* d_in, const int* in_sizes, int n_in,
                              void* d_out, int out_size) {
    const float* x_sub      = (const float*)d_in[0];
    const int*   ei_sub     = (const int*)  d_in[1];
    const int*   batch_sub  = (const int*)  d_in[2];
    const int*   sub_index  = (const int*)  d_in[3];
    const float* x_glob     = (const float*)d_in[4];
    const int*   ei_glob    = (const int*)  d_in[5];
    const int*   batch_glob = (const int*)  d_in[6];
    const float* W_sub      = (const float*)d_in[7];
    const float* b_sub      = (const float*)d_in[8];
    const float* W_glob     = (const float*)d_in[9];
    const float* b_glob     = (const float*)d_in[10];
    const float* fc_W       = (const float*)d_in[11];
    const float* fc_b       = (const float*)d_in[12];
    float* out = (float*)d_out;

    const int E_sub  = in_sizes[1] / 2;
    const int E_glob = in_sizes[5] / 2;

    static bool init = false;
    static float *p_dis_sub, *p_dis_glob, *p_pooled, *p_p2;
    static int *p_cd_sub, *p_cd_glob, *p_off_sub, *p_off_glob, *p_cur_sub, *p_cur_glob,
               *p_csr_sub, *p_csr_glob;
    static __nv_bfloat16 *pb_a_sub, *pb_a_glob, *pb_a_pool, *pb_wt_sub, *pb_wt_glob,
                         *p_hs_sub, *p_hs_glob;
    if (!init) {
        init = true;
        cudaGetSymbolAddress((void**)&p_dis_sub,  g_dis_sub);
        cudaGetSymbolAddress((void**)&p_dis_glob, g_dis_glob);
        cudaGetSymbolAddress((void**)&p_pooled,   g_pooled);
        cudaGetSymbolAddress((void**)&p_p2,       g_p2);
        cudaGetSymbolAddress((void**)&p_cd_sub,   g_cntdeg_sub);
        cudaGetSymbolAddress((void**)&p_cd_glob,  g_cntdeg_glob);
        cudaGetSymbolAddress((void**)&p_off_sub,  g_off_sub);
        cudaGetSymbolAddress((void**)&p_off_glob, g_off_glob);
        cudaGetSymbolAddress((void**)&p_cur_sub,  g_cur_sub);
        cudaGetSymbolAddress((void**)&p_cur_glob, g_cur_glob);
        cudaGetSymbolAddress((void**)&p_csr_sub,  g_csr_sub);
        cudaGetSymbolAddress((void**)&p_csr_glob, g_csr_glob);
        cudaGetSymbolAddress((void**)&pb_a_sub,   g_bA_sub);
        cudaGetSymbolAddress((void**)&pb_a_glob,  g_bA_glob);
        cudaGetSymbolAddress((void**)&pb_a_pool,  g_bA_pool);
        cudaGetSymbolAddress((void**)&pb_wt_sub,  g_bWt_sub);
        cudaGetSymbolAddress((void**)&pb_wt_glob, g_bWt_glob);
        cudaGetSymbolAddress((void**)&p_hs_sub,   g_hs_sub);
        cudaGetSymbolAddress((void**)&p_hs_glob,  g_hs_glob);
        cudaFuncSetAttribute(k_gemm_mma, cudaFuncAttributeMaxDynamicSharedMemorySize, GEMM_SMEM);
    }

    // init + CSR build (both graphs)
    k_zero_misc  <<<(SSEG * HDIM + 255) / 256, 256>>>();
    k_prefill_csr<<<(CAPG + 255) / 256, 256>>>();
    k_hist<<<(E_sub  + 255) / 256, 256>>>(p_cd_sub,  ei_sub,  E_sub);
    k_hist<<<(E_glob + 255) / 256, 256>>>(p_cd_glob, ei_glob, E_glob);
    k_dis <<<(NSUB  + 255) / 256, 256>>>(p_dis_sub,  p_cd_sub,  NSUB);
    k_dis <<<(NGLOB + 255) / 256, 256>>>(p_dis_glob, p_cd_glob, NGLOB);
    k_scan<<<1, 1024>>>(p_cd_sub,  p_off_sub,  p_cur_sub,  NSUB);
    k_scan<<<1, 1024>>>(p_cd_glob, p_off_glob, p_cur_glob, NGLOB);
    k_fill<<<(E_sub  + 255) / 256, 256>>>(p_csr_sub,  p_cur_sub,  ei_sub,  E_sub);
    k_fill<<<(E_glob + 255) / 256, 256>>>(p_csr_glob, p_cur_glob, ei_glob, E_glob);

    // ---- sub conv: hs_sub = (x_sub @ W_sub) * dis ----
    k_pack_Wt<<<dim3(8, 8), 256>>>(W_sub, pb_wt_sub);
    k_pack_A <<<(NSUB * 64 + 255) / 256, 256>>>(x_sub, pb_a_sub, NSUB);
    k_gemm_mma<<<dim3(NSUB / 128, 2), 256, GEMM_SMEM>>>(pb_a_sub, pb_wt_sub,
                                                        p_hs_sub, nullptr, p_dis_sub);
    k_cnt_sub<<<(NSUB + 255) / 256, 256>>>(batch_sub, NSUB);
    k_gather_sub<<<NSUB / 32, 256>>>(batch_sub, b_sub);
    k_pool_div<<<(SSEG * HDIM + 255) / 256, 256>>>();

    // ---- glob conv ----
    k_pack_Wt<<<dim3(8, 8), 256>>>(W_glob, pb_wt_glob);
    k_pack_A <<<(NGLOB * 64 + 255) / 256, 256>>>(x_glob, pb_a_glob, NGLOB);
    k_gemm_mma<<<dim3(NGLOB / 128, 2), 256, GEMM_SMEM>>>(pb_a_glob, pb_wt_glob,
                                                         p_hs_glob, nullptr, p_dis_glob);
    k_pack_A <<<(SSEG * 64 + 255) / 256, 256>>>(p_pooled, pb_a_pool, SSEG);
    k_gemm_mma<<<dim3(SSEG / 128, 2), 256, GEMM_SMEM>>>(pb_a_pool, pb_wt_glob,
                                                        nullptr, p_p2, nullptr);
    k_inject<<<(SSEG * 128 + 255) / 256, 256>>>(sub_index);
    k_gather_glob<<<NGLOB / 32, 256>>>(batch_glob, b_glob);

    k_final<<<1, 256>>>(fc_W, fc_b, out);
}

// round 5
// speedup vs baseline: 5.8847x; 2.0742x over previous
#include <cuda_runtime.h>
#include <cuda_bf16.h>
#include <cstdint>

#define HDIM   256
#define NSUB   32768
#define NGLOB  65536
#define SSEG   1024
#define ESUB_MAX   262144
#define EGLOB_MAX  1048576
#define CAPS (ESUB_MAX  + 4 * NSUB)
#define CAPG (EGLOB_MAX + 4 * NGLOB)

// ---------------- scratch ----------------
__device__ float g_dis_sub[NSUB];
__device__ float g_dis_glob[NGLOB];
__device__ float g_pooled[SSEG * HDIM];
__device__ float g_cnt[SSEG];
__device__ float g_p2[SSEG * HDIM];
__device__ float g_gemb_part[64 * HDIM];
__device__ int   g_gcnt;

__device__ int g_cntdeg_sub[NSUB];
__device__ int g_cntdeg_glob[NGLOB];
__device__ int g_off_sub[NSUB + 1];
__device__ int g_off_glob[NGLOB + 1];
__device__ int g_cur_sub[NSUB];
__device__ int g_cur_glob[NGLOB];
__device__ int g_bsum_sub[NSUB / 256];
__device__ int g_bsum_glob[NGLOB / 256];
__device__ __align__(16) int g_csr_sub[CAPS];
__device__ __align__(16) int g_csr_glob[CAPG];

__device__ __align__(16) __nv_bfloat16 g_hs_sub [(NSUB  + 1) * HDIM];
__device__ __align__(16) __nv_bfloat16 g_hs_glob[(NGLOB + 1) * HDIM];
__device__ __align__(16) __nv_bfloat16 g_bA_sub [NSUB  * HDIM];
__device__ __align__(16) __nv_bfloat16 g_bA_glob[NGLOB * HDIM];
__device__ __align__(16) __nv_bfloat16 g_bA_pool[SSEG  * HDIM];
__device__ __align__(16) __nv_bfloat16 g_bWt_sub [HDIM * HDIM];
__device__ __align__(16) __nv_bfloat16 g_bWt_glob[HDIM * HDIM];

// ---------------- PTX helpers ----------------
__device__ __forceinline__ void red4(float* p, float x, float y, float z, float w) {
    asm volatile("red.global.add.v4.f32 [%0], {%1, %2, %3, %4};"
                 :: "l"(p), "f"(x), "f"(y), "f"(z), "f"(w) : "memory");
}
__device__ __forceinline__ void cp_async16(uint32_t dst, const void* src) {
    asm volatile("cp.async.cg.shared.global [%0], [%1], 16;" :: "r"(dst), "l"(src) : "memory");
}
__device__ __forceinline__ void cp_commit() {
    asm volatile("cp.async.commit_group;" ::: "memory");
}
template <int N>
__device__ __forceinline__ void cp_wait() {
    asm volatile("cp.async.wait_group %0;" :: "n"(N) : "memory");
}
__device__ __forceinline__ void ldsm_x4(uint32_t& r0, uint32_t& r1, uint32_t& r2, uint32_t& r3,
                                        uint32_t addr) {
    asm volatile("ldmatrix.sync.aligned.m8n8.x4.shared.b16 {%0,%1,%2,%3}, [%4];"
                 : "=r"(r0), "=r"(r1), "=r"(r2), "=r"(r3) : "r"(addr));
}
__device__ __forceinline__ void mma_bf16(float* c, const uint32_t* a, const uint32_t* b) {
    asm volatile(
        "mma.sync.aligned.m16n8k16.row.col.f32.bf16.bf16.f32 "
        "{%0,%1,%2,%3}, {%4,%5,%6,%7}, {%8,%9}, {%0,%1,%2,%3};"
        : "+f"(c[0]), "+f"(c[1]), "+f"(c[2]), "+f"(c[3])
        : "r"(a[0]), "r"(a[1]), "r"(a[2]), "r"(a[3]), "r"(b[0]), "r"(b[1]));
}
__device__ __forceinline__ __nv_bfloat162 badd2(__nv_bfloat162 a, __nv_bfloat162 b) {
    return __hadd2(a, b);
}

// ---------------- init ----------------
__global__ void k_zero_misc() {
    int i = blockIdx.x * blockDim.x + threadIdx.x;   // grid covers 262144
    if (i < SSEG * HDIM) g_pooled[i] = 0.0f;
    if (i < 64 * HDIM)   g_gemb_part[i] = 0.0f;
    if (i < SSEG)        g_cnt[i] = 0.0f;
    if (i < NGLOB)       g_cntdeg_glob[i] = 0;
    if (i < NSUB)        g_cntdeg_sub[i]  = 0;
    if (i < HDIM) {
        g_hs_sub [NSUB  * HDIM + i] = __float2bfloat16(0.0f);
        g_hs_glob[NGLOB * HDIM + i] = __float2bfloat16(0.0f);
    }
    if (i == 0) g_gcnt = 0;
}
__global__ void k_hist(int* __restrict__ cnt, const int* __restrict__ ei, int E) {
    int i = blockIdx.x * blockDim.x + threadIdx.x;
    if (i < E) atomicAdd(&cnt[ei[E + i]], 1);
}

// ---- parallel padded-degree scan: phase1 block sums (+dis), phase2 scan sums, phase3 offsets
__global__ void k_scan1(const int* __restrict__ cnt, float* __restrict__ dis,
                        int* __restrict__ bsum) {
    __shared__ int sh[8];
    int i = blockIdx.x * 256 + threadIdx.x;
    int c = cnt[i];
    dis[i] = rsqrtf((float)c + 1.0f);
    int p = (c + 3) & ~3;
    for (int o = 16; o; o >>= 1) p += __shfl_down_sync(~0u, p, o);
    if ((threadIdx.x & 31) == 0) sh[threadIdx.x >> 5] = p;
    __syncthreads();
    if (threadIdx.x < 8) {
        int v = sh[threadIdx.x];
        for (int o = 4; o; o >>= 1) v += __shfl_down_sync(0xff, v, o);
        if (threadIdx.x == 0) bsum[blockIdx.x] = v;
    }
}
__global__ void k_scan2(int* __restrict__ bsum, int NB) {   // 1 block, 256 threads
    __shared__ int sh[256];
    int t = threadIdx.x;
    int v = (t < NB) ? bsum[t] : 0;
    sh[t] = v;
    __syncthreads();
    for (int d = 1; d < 256; d <<= 1) {
        int u = (t >= d) ? sh[t - d] : 0;
        __syncthreads();
        sh[t] += u;
        __syncthreads();
    }
    if (t < NB) bsum[t] = sh[t] - v;   // exclusive
}
__global__ void k_scan3(const int* __restrict__ cnt, const int* __restrict__ bsum,
                        int* __restrict__ off, int* __restrict__ cur, int N) {
    __shared__ int sh[256];
    int t = threadIdx.x;
    int i = blockIdx.x * 256 + t;
    int c = cnt[i];
    int p = (c + 3) & ~3;
    sh[t] = p;
    __syncthreads();
    for (int d = 1; d < 256; d <<= 1) {
        int u = (t >= d) ? sh[t - d] : 0;
        __syncthreads();
        sh[t] += u;
        __syncthreads();
    }
    int excl = sh[t] - p + bsum[blockIdx.x];
    off[i] = excl;
    cur[i] = excl;
    if (i == N - 1) off[N] = excl + p;
}
__global__ void k_fill(int* __restrict__ csr, int* __restrict__ cur,
                       const int* __restrict__ ei, int E) {
    int i = blockIdx.x * blockDim.x + threadIdx.x;
    if (i >= E) return;
    int p = atomicAdd(&cur[ei[E + i]], 1);
    csr[p] = ei[i];
}
__global__ void k_pad(const int* __restrict__ cnt, const int* __restrict__ off,
                      int* __restrict__ csr, int N) {
    int i = blockIdx.x * blockDim.x + threadIdx.x;
    if (i >= N) return;
    int c = cnt[i], o = off[i], p = (c + 3) & ~3;
    for (int j = c; j < p; j++) csr[o + j] = N;   // sentinel -> zero row
}

// ---------------- packs ----------------
__global__ void k_pack_A(const float* __restrict__ A, __nv_bfloat16* __restrict__ out, int M) {
    int vid = blockIdx.x * blockDim.x + threadIdx.x;
    if (vid >= M * 64) return;
    float4 v = ((const float4*)A)[vid];
    __nv_bfloat162 lo = __floats2bfloat162_rn(v.x, v.y);
    __nv_bfloat162 hi = __floats2bfloat162_rn(v.z, v.w);
    ((uint2*)out)[vid] = make_uint2(*reinterpret_cast<uint32_t*>(&lo),
                                    *reinterpret_cast<uint32_t*>(&hi));
}
__global__ void k_pack_Wt(const float* __restrict__ W, __nv_bfloat16* __restrict__ out) {
    __shared__ float tile[32][33];
    int bx = blockIdx.x * 32, by = blockIdx.y * 32;
    int tx = threadIdx.x & 31, ty = threadIdx.x >> 5;
    for (int i = 0; i < 32; i += 8)
        tile[ty + i][tx] = W[(by + ty + i) * HDIM + bx + tx];
    __syncthreads();
    for (int i = 0; i < 32; i += 8)
        out[(bx + ty + i) * HDIM + by + tx] = __float2bfloat16(tile[tx][ty + i]);
}

// ---------------- bf16 mma GEMM (same as R4) ----------------
#define GEMM_SMEM (4 * 16384)
__global__ __launch_bounds__(256, 2) void k_gemm_mma(
    const __nv_bfloat16* __restrict__ A,
    const __nv_bfloat16* __restrict__ Wt,
    __nv_bfloat16* __restrict__ Hs,
    float* __restrict__ Cf,
    const float* __restrict__ dis)
{
    extern __shared__ __align__(16) unsigned char smem[];
    const int tid  = threadIdx.x;
    const int lane = tid & 31, warp = tid >> 5;
    const int wm = warp & 3, wn = warp >> 2;
    const int row0 = blockIdx.x * 128, col0 = blockIdx.y * 128;
    uint32_t sbase = (uint32_t)__cvta_generic_to_shared(smem);

    float acc[2][8][4];
#pragma unroll
    for (int mt = 0; mt < 2; mt++)
#pragma unroll
        for (int nt = 0; nt < 8; nt++)
#pragma unroll
            for (int i = 0; i < 4; i++) acc[mt][nt][i] = 0.0f;

    auto load_stage = [&](int s, int kc) {
        const __nv_bfloat16* Ag = A  + (size_t)(row0)*HDIM + kc * 64;
        const __nv_bfloat16* Bg = Wt + (size_t)(col0)*HDIM + kc * 64;
        uint32_t sA = sbase + s * 16384;
        uint32_t sB = sbase + 32768 + s * 16384;
#pragma unroll
        for (int i = 0; i < 4; i++) {
            int id = tid + i * 256;
            int r = id >> 3, c = id & 7;
            uint32_t d = (uint32_t)(r * 128 + ((c ^ (r & 7)) << 4));
            cp_async16(sA + d, Ag + (size_t)r * HDIM + c * 8);
            cp_async16(sB + d, Bg + (size_t)r * HDIM + c * 8);
        }
        cp_commit();
    };

    load_stage(0, 0);
    int s = 0;
#pragma unroll 1
    for (int kc = 0; kc < 4; kc++) {
        if (kc < 3) load_stage(s ^ 1, kc + 1);
        if (kc < 3) cp_wait<1>(); else cp_wait<0>();
        __syncthreads();
        uint32_t sA = sbase + s * 16384;
        uint32_t sB = sbase + 32768 + s * 16384;
#pragma unroll
        for (int kk = 0; kk < 4; kk++) {
            uint32_t af[2][4];
#pragma unroll
            for (int mt = 0; mt < 2; mt++) {
                int r = wm * 32 + mt * 16 + (lane & 15);
                int c = kk * 2 + (lane >> 4);
                ldsm_x4(af[mt][0], af[mt][1], af[mt][2], af[mt][3],
                        sA + r * 128 + ((c ^ (r & 7)) << 4));
            }
            uint32_t bf[8][2];
#pragma unroll
            for (int p = 0; p < 4; p++) {
                int r = wn * 64 + p * 16 + ((lane >> 4) << 3) + (lane & 7);
                int c = kk * 2 + ((lane >> 3) & 1);
                ldsm_x4(bf[2 * p][0], bf[2 * p][1], bf[2 * p + 1][0], bf[2 * p + 1][1],
                        sB + r * 128 + ((c ^ (r & 7)) << 4));
            }
#pragma unroll
            for (int mt = 0; mt < 2; mt++)
#pragma unroll
                for (int nt = 0; nt < 8; nt++)
                    mma_bf16(acc[mt][nt], af[mt], bf[nt]);
        }
        __syncthreads();
        s ^= 1;
    }

    const int g = lane >> 2, t4 = lane & 3;
#pragma unroll
    for (int mt = 0; mt < 2; mt++) {
        int r_lo = row0 + wm * 32 + mt * 16 + g;
        int r_hi = r_lo + 8;
        if (dis) {
            float dlo = dis[r_lo], dhi = dis[r_hi];
#pragma unroll
            for (int nt = 0; nt < 8; nt++) {
                int col = col0 + wn * 64 + nt * 8 + 2 * t4;
                __nv_bfloat162 lo = __floats2bfloat162_rn(acc[mt][nt][0] * dlo,
                                                          acc[mt][nt][1] * dlo);
                __nv_bfloat162 hi = __floats2bfloat162_rn(acc[mt][nt][2] * dhi,
                                                          acc[mt][nt][3] * dhi);
                *(__nv_bfloat162*)&Hs[(size_t)r_lo * HDIM + col] = lo;
                *(__nv_bfloat162*)&Hs[(size_t)r_hi * HDIM + col] = hi;
            }
        } else {
#pragma unroll
            for (int nt = 0; nt < 8; nt++) {
                int col = col0 + wn * 64 + nt * 8 + 2 * t4;
                *(float2*)&Cf[(size_t)r_lo * HDIM + col] =
                    make_float2(acc[mt][nt][0], acc[mt][nt][1]);
                *(float2*)&Cf[(size_t)r_hi * HDIM + col] =
                    make_float2(acc[mt][nt][2], acc[mt][nt][3]);
            }
        }
    }
}

// ---------------- CSR gather + fused epilogues (same as R4) ----------------
__global__ __launch_bounds__(256) void k_gather_sub(
    const int* __restrict__ batch, const float* __restrict__ bias)
{
    const int lane = threadIdx.x & 31, grp = threadIdx.x >> 5;
    const uint4* H = (const uint4*)g_hs_sub;
    float4 b0 = ((const float4*)bias)[lane * 2];
    float4 b1 = ((const float4*)bias)[lane * 2 + 1];
#pragma unroll 1
    for (int it = 0; it < 4; it++) {
        int n = blockIdx.x * 32 + it * 8 + grp;
        int o0 = g_off_sub[n] >> 2, o1 = g_off_sub[n + 1] >> 2;
        uint4 a = H[(size_t)n * 32 + lane];
        __nv_bfloat162 A0 = *(__nv_bfloat162*)&a.x, A1 = *(__nv_bfloat162*)&a.y,
                       A2 = *(__nv_bfloat162*)&a.z, A3 = *(__nv_bfloat162*)&a.w;
#pragma unroll 1
        for (int k = o0; k < o1; k++) {
            int4 s4 = ((const int4*)g_csr_sub)[k];
            uint4 v;
            v = H[(size_t)s4.x * 32 + lane];
            A0 = badd2(A0, *(__nv_bfloat162*)&v.x); A1 = badd2(A1, *(__nv_bfloat162*)&v.y);
            A2 = badd2(A2, *(__nv_bfloat162*)&v.z); A3 = badd2(A3, *(__nv_bfloat162*)&v.w);
            v = H[(size_t)s4.y * 32 + lane];
            A0 = badd2(A0, *(__nv_bfloat162*)&v.x); A1 = badd2(A1, *(__nv_bfloat162*)&v.y);
            A2 = badd2(A2, *(__nv_bfloat162*)&v.z); A3 = badd2(A3, *(__nv_bfloat162*)&v.w);
            v = H[(size_t)s4.z * 32 + lane];
            A0 = badd2(A0, *(__nv_bfloat162*)&v.x); A1 = badd2(A1, *(__nv_bfloat162*)&v.y);
            A2 = badd2(A2, *(__nv_bfloat162*)&v.z); A3 = badd2(A3, *(__nv_bfloat162*)&v.w);
            v = H[(size_t)s4.w * 32 + lane];
            A0 = badd2(A0, *(__nv_bfloat162*)&v.x); A1 = badd2(A1, *(__nv_bfloat162*)&v.y);
            A2 = badd2(A2, *(__nv_bfloat162*)&v.z); A3 = badd2(A3, *(__nv_bfloat162*)&v.w);
        }
        float d = g_dis_sub[n];
        float2 f0 = __bfloat1622float2(A0), f1 = __bfloat1622float2(A1);
        float2 f2 = __bfloat1622float2(A2), f3 = __bfloat1622float2(A3);
        float* dst = g_pooled + (size_t)batch[n] * HDIM + lane * 8;
        red4(dst,
             fmaxf(fmaf(f0.x, d, b0.x), 0.0f), fmaxf(fmaf(f0.y, d, b0.y), 0.0f),
             fmaxf(fmaf(f1.x, d, b0.z), 0.0f), fmaxf(fmaf(f1.y, d, b0.w), 0.0f));
        red4(dst + 4,
             fmaxf(fmaf(f2.x, d, b1.x), 0.0f), fmaxf(fmaf(f2.y, d, b1.y), 0.0f),
             fmaxf(fmaf(f3.x, d, b1.z), 0.0f), fmaxf(fmaf(f3.y, d, b1.w), 0.0f));
    }
}

__global__ __launch_bounds__(256) void k_gather_glob(
    const int* __restrict__ batch, const float* __restrict__ bias)
{
    const int lane = threadIdx.x & 31, grp = threadIdx.x >> 5;
    const uint4* H = (const uint4*)g_hs_glob;
    float4 b0 = ((const float4*)bias)[lane * 2];
    float4 b1 = ((const float4*)bias)[lane * 2 + 1];
    float r0 = 0, r1 = 0, r2 = 0, r3 = 0, r4 = 0, r5 = 0, r6 = 0, r7 = 0;
    int cloc = 0;
#pragma unroll 1
    for (int it = 0; it < 4; it++) {
        int n = blockIdx.x * 32 + it * 8 + grp;
        int o0 = g_off_glob[n] >> 2, o1 = g_off_glob[n + 1] >> 2;
        uint4 a = H[(size_t)n * 32 + lane];
        __nv_bfloat162 A0 = *(__nv_bfloat162*)&a.x, A1 = *(__nv_bfloat162*)&a.y,
                       A2 = *(__nv_bfloat162*)&a.z, A3 = *(__nv_bfloat162*)&a.w;
#pragma unroll 1
        for (int k = o0; k < o1; k++) {
            int4 s4 = ((const int4*)g_csr_glob)[k];
            uint4 v;
            v = H[(size_t)s4.x * 32 + lane];
            A0 = badd2(A0, *(__nv_bfloat162*)&v.x); A1 = badd2(A1, *(__nv_bfloat162*)&v.y);
            A2 = badd2(A2, *(__nv_bfloat162*)&v.z); A3 = badd2(A3, *(__nv_bfloat162*)&v.w);
            v = H[(size_t)s4.y * 32 + lane];
            A0 = badd2(A0, *(__nv_bfloat162*)&v.x); A1 = badd2(A1, *(__nv_bfloat162*)&v.y);
            A2 = badd2(A2, *(__nv_bfloat162*)&v.z); A3 = badd2(A3, *(__nv_bfloat162*)&v.w);
            v = H[(size_t)s4.z * 32 + lane];
            A0 = badd2(A0, *(__nv_bfloat162*)&v.x); A1 = badd2(A1, *(__nv_bfloat162*)&v.y);
            A2 = badd2(A2, *(__nv_bfloat162*)&v.z); A3 = badd2(A3, *(__nv_bfloat162*)&v.w);
            v = H[(size_t)s4.w * 32 + lane];
            A0 = badd2(A0, *(__nv_bfloat162*)&v.x); A1 = badd2(A1, *(__nv_bfloat162*)&v.y);
            A2 = badd2(A2, *(__nv_bfloat162*)&v.z); A3 = badd2(A3, *(__nv_bfloat162*)&v.w);
        }
        if (batch[n] == 0) {
            float d = g_dis_glob[n];
            float2 f0 = __bfloat1622float2(A0), f1 = __bfloat1622float2(A1);
            float2 f2 = __bfloat1622float2(A2), f3 = __bfloat1622float2(A3);
            r0 += fmaxf(fmaf(f0.x, d, b0.x), 0.0f);
            r1 += fmaxf(fmaf(f0.y, d, b0.y), 0.0f);
            r2 += fmaxf(fmaf(f1.x, d, b0.z), 0.0f);
            r3 += fmaxf(fmaf(f1.y, d, b0.w), 0.0f);
            r4 += fmaxf(fmaf(f2.x, d, b1.x), 0.0f);
            r5 += fmaxf(fmaf(f2.y, d, b1.y), 0.0f);
            r6 += fmaxf(fmaf(f3.x, d, b1.z), 0.0f);
            r7 += fmaxf(fmaf(f3.y, d, b1.w), 0.0f);
            cloc++;
        }
    }
    float* dst = g_gemb_part + (size_t)(blockIdx.x & 63) * HDIM + lane * 8;
    red4(dst, r0, r1, r2, r3);
    red4(dst + 4, r4, r5, r6, r7);
    if (lane == 0) atomicAdd(&g_gcnt, cloc);
}

// ---------------- misc ----------------
__global__ void k_cnt_sub(const int* __restrict__ batch, int N) {
    int i = blockIdx.x * blockDim.x + threadIdx.x;
    if (i < N) atomicAdd(&g_cnt[batch[i]], 1.0f);
}
__global__ void k_pool_div() {
    int idx = blockIdx.x * blockDim.x + threadIdx.x;
    if (idx >= SSEG * HDIM) return;
    int s = idx >> 8;
    g_pooled[idx] /= fmaxf(g_cnt[s], 1.0f);
}
__global__ void k_inject(const int* __restrict__ sub_index) {
    int idx = blockIdx.x * blockDim.x + threadIdx.x;
    if (idx >= SSEG * 128) return;
    int s = idx >> 7, c2 = idx & 127;
    int node = sub_index[s];
    float d = g_dis_glob[node];
    __nv_bfloat162* hp = (__nv_bfloat162*)g_hs_glob + (size_t)node * 128 + c2;
    float2 h = __bfloat1622float2(*hp);
    const float* p = g_p2 + (size_t)s * HDIM + c2 * 2;
    *hp = __floats2bfloat162_rn(fmaf(p[0], d, h.x), fmaf(p[1], d, h.y));
}
__global__ void k_final(const float* __restrict__ fc_W, const float* __restrict__ fc_b,
                        float* __restrict__ out) {
    __shared__ float sg[HDIM];
    int t = threadIdx.x;
    float s = 0.0f;
#pragma unroll 8
    for (int p = 0; p < 64; p++) s += g_gemb_part[p * HDIM + t];
    sg[t] = s / fmaxf((float)g_gcnt, 1.0f);
    __syncthreads();
    float acc = fc_b[t];
    const float* wr = fc_W + (size_t)t * HDIM;
#pragma unroll 8
    for (int h = 0; h < HDIM; h++) acc = fmaf(sg[h], wr[h], acc);
    out[t] = acc;
}

// ---------------- host launcher ----------------
extern "C" void kernel_launch(void* const* d_in, const int* in_sizes, int n_in,
                              void* d_out, int out_size) {
    const float* x_sub      = (const float*)d_in[0];
    const int*   ei_sub     = (const int*)  d_in[1];
    const int*   batch_sub  = (const int*)  d_in[2];
    const int*   sub_index  = (const int*)  d_in[3];
    const float* x_glob     = (const float*)d_in[4];
    const int*   ei_glob    = (const int*)  d_in[5];
    const int*   batch_glob = (const int*)  d_in[6];
    const float* W_sub      = (const float*)d_in[7];
    const float* b_sub      = (const float*)d_in[8];
    const float* W_glob     = (const float*)d_in[9];
    const float* b_glob     = (const float*)d_in[10];
    const float* fc_W       = (const float*)d_in[11];
    const float* fc_b       = (const float*)d_in[12];
    float* out = (float*)d_out;

    const int E_sub  = in_sizes[1] / 2;
    const int E_glob = in_sizes[5] / 2;

    static bool init = false;
    static float *p_dis_sub, *p_dis_glob, *p_pooled, *p_p2;
    static int *p_cd_sub, *p_cd_glob, *p_off_sub, *p_off_glob, *p_cur_sub, *p_cur_glob,
               *p_csr_sub, *p_csr_glob, *p_bs_sub, *p_bs_glob;
    static __nv_bfloat16 *pb_a_sub, *pb_a_glob, *pb_a_pool, *pb_wt_sub, *pb_wt_glob,
                         *p_hs_sub, *p_hs_glob;
    static cudaStream_t s2;
    static cudaEvent_t eStart, eZ, ePW, eG;
    if (!init) {
        init = true;
        cudaGetSymbolAddress((void**)&p_dis_sub,  g_dis_sub);
        cudaGetSymbolAddress((void**)&p_dis_glob, g_dis_glob);
        cudaGetSymbolAddress((void**)&p_pooled,   g_pooled);
        cudaGetSymbolAddress((void**)&p_p2,       g_p2);
        cudaGetSymbolAddress((void**)&p_cd_sub,   g_cntdeg_sub);
        cudaGetSymbolAddress((void**)&p_cd_glob,  g_cntdeg_glob);
        cudaGetSymbolAddress((void**)&p_off_sub,  g_off_sub);
        cudaGetSymbolAddress((void**)&p_off_glob, g_off_glob);
        cudaGetSymbolAddress((void**)&p_cur_sub,  g_cur_sub);
        cudaGetSymbolAddress((void**)&p_cur_glob, g_cur_glob);
        cudaGetSymbolAddress((void**)&p_csr_sub,  g_csr_sub);
        cudaGetSymbolAddress((void**)&p_csr_glob, g_csr_glob);
        cudaGetSymbolAddress((void**)&p_bs_sub,   g_bsum_sub);
        cudaGetSymbolAddress((void**)&p_bs_glob,  g_bsum_glob);
        cudaGetSymbolAddress((void**)&pb_a_sub,   g_bA_sub);
        cudaGetSymbolAddress((void**)&pb_a_glob,  g_bA_glob);
        cudaGetSymbolAddress((void**)&pb_a_pool,  g_bA_pool);
        cudaGetSymbolAddress((void**)&pb_wt_sub,  g_bWt_sub);
        cudaGetSymbolAddress((void**)&pb_wt_glob, g_bWt_glob);
        cudaGetSymbolAddress((void**)&p_hs_sub,   g_hs_sub);
        cudaGetSymbolAddress((void**)&p_hs_glob,  g_hs_glob);
        cudaFuncSetAttribute(k_gemm_mma, cudaFuncAttributeMaxDynamicSharedMemorySize, GEMM_SMEM);
        cudaStreamCreateWithFlags(&s2, cudaStreamNonBlocking);
        cudaEventCreateWithFlags(&eStart, cudaEventDisableTiming);
        cudaEventCreateWithFlags(&eZ,     cudaEventDisableTiming);
        cudaEventCreateWithFlags(&ePW,    cudaEventDisableTiming);
        cudaEventCreateWithFlags(&eG,     cudaEventDisableTiming);
    }

    // ---- fork side stream ----
    cudaEventRecord(eStart, 0);
    cudaStreamWaitEvent(s2, eStart, 0);

    // stream 0: init
    k_zero_misc<<<1024, 256>>>();
    cudaEventRecord(eZ, 0);

    // ---- side stream s2: glob branch (packs, CSR build, big GEMM) ----
    k_pack_Wt<<<dim3(8, 8), 256, 0, s2>>>(W_glob, pb_wt_glob);
    cudaEventRecord(ePW, s2);
    k_pack_A <<<(NGLOB * 64 + 255) / 256, 256, 0, s2>>>(x_glob, pb_a_glob, NGLOB);
    cudaStreamWaitEvent(s2, eZ, 0);
    k_hist <<<(E_glob + 255) / 256, 256, 0, s2>>>(p_cd_glob, ei_glob, E_glob);
    k_scan1<<<NGLOB / 256, 256, 0, s2>>>(p_cd_glob, p_dis_glob, p_bs_glob);
    k_scan2<<<1, 256, 0, s2>>>(p_bs_glob, NGLOB / 256);
    k_scan3<<<NGLOB / 256, 256, 0, s2>>>(p_cd_glob, p_bs_glob, p_off_glob, p_cur_glob, NGLOB);
    k_fill <<<(E_glob + 255) / 256, 256, 0, s2>>>(p_csr_glob, p_cur_glob, ei_glob, E_glob);
    k_pad  <<<NGLOB / 256, 256, 0, s2>>>(p_cd_glob, p_off_glob, p_csr_glob, NGLOB);
    k_gemm_mma<<<dim3(NGLOB / 128, 2), 256, GEMM_SMEM, s2>>>(pb_a_glob, pb_wt_glob,
                                                             p_hs_glob, nullptr, p_dis_glob);
    cudaEventRecord(eG, s2);

    // ---- stream 0: sub branch ----
    k_hist <<<(E_sub + 255) / 256, 256>>>(p_cd_sub, ei_sub, E_sub);
    k_scan1<<<NSUB / 256, 256>>>(p_cd_sub, p_dis_sub, p_bs_sub);
    k_scan2<<<1, 256>>>(p_bs_sub, NSUB / 256);
    k_scan3<<<NSUB / 256, 256>>>(p_cd_sub, p_bs_sub, p_off_sub, p_cur_sub, NSUB);
    k_fill <<<(E_sub + 255) / 256, 256>>>(p_csr_sub, p_cur_sub, ei_sub, E_sub);
    k_pad  <<<NSUB / 256, 256>>>(p_cd_sub, p_off_sub, p_csr_sub, NSUB);
    k_pack_Wt<<<dim3(8, 8), 256>>>(W_sub, pb_wt_sub);
    k_pack_A <<<(NSUB * 64 + 255) / 256, 256>>>(x_sub, pb_a_sub, NSUB);
    k_gemm_mma<<<dim3(NSUB / 128, 2), 256, GEMM_SMEM>>>(pb_a_sub, pb_wt_sub,
                                                        p_hs_sub, nullptr, p_dis_sub);
    k_cnt_sub<<<(NSUB + 255) / 256, 256>>>(batch_sub, NSUB);
    k_gather_sub<<<NSUB / 32, 256>>>(batch_sub, b_sub);
    k_pool_div<<<(SSEG * HDIM + 255) / 256, 256>>>();
    k_pack_A <<<(SSEG * 64 + 255) / 256, 256>>>(p_pooled, pb_a_pool, SSEG);
    cudaStreamWaitEvent(0, ePW, 0);
    k_gemm_mma<<<dim3(SSEG / 128, 2), 256, GEMM_SMEM>>>(pb_a_pool, pb_wt_glob,
                                                        nullptr, p_p2, nullptr);

    // ---- join: inject + global gather + final ----
    cudaStreamWaitEvent(0, eG, 0);
    k_inject<<<(SSEG * 128 + 255) / 256, 256>>>(sub_index);
    k_gather_glob<<<NGLOB / 32, 256>>>(batch_glob, b_glob);
    k_final<<<1, 256>>>(fc_W, fc_b, out);
}

// round 6
// speedup vs baseline: 6.0529x; 1.0286x over previous
#include <cuda_runtime.h>
#include <cuda_bf16.h>
#include <cstdint>

#define HDIM   256
#define NSUB   32768
#define NGLOB  65536
#define SSEG   1024
#define ESUB_MAX   262144
#define EGLOB_MAX  1048576
#define CAPS (ESUB_MAX  + 4 * NSUB)
#define CAPG (EGLOB_MAX + 4 * NGLOB)

// ---------------- scratch ----------------
__device__ float g_dis_sub[NSUB];
__device__ float g_dis_glob[NGLOB];
__device__ float g_pooled[SSEG * HDIM];
__device__ float g_cnt[SSEG];
__device__ float g_p2[SSEG * HDIM];
__device__ float g_gemb_part[64 * HDIM];
__device__ int   g_gcnt;

__device__ int g_cntdeg_sub[NSUB];
__device__ int g_cntdeg_glob[NGLOB];
__device__ int g_off_sub[NSUB + 1];
__device__ int g_off_glob[NGLOB + 1];
__device__ int g_cur_sub[NSUB];
__device__ int g_cur_glob[NGLOB];
__device__ int g_bsum_sub[NSUB / 256];
__device__ int g_bsum_glob[NGLOB / 256];
__device__ __align__(16) int g_csr_sub[CAPS];
__device__ __align__(16) int g_csr_glob[CAPG];

__device__ __align__(16) __nv_bfloat16 g_hs_sub [(NSUB  + 1) * HDIM];
__device__ __align__(16) __nv_bfloat16 g_hs_glob[(NGLOB + 1) * HDIM];
__device__ __align__(16) __nv_bfloat16 g_bA_sub [NSUB  * HDIM];
__device__ __align__(16) __nv_bfloat16 g_bA_glob[NGLOB * HDIM];
__device__ __align__(16) __nv_bfloat16 g_bA_pool[SSEG  * HDIM];
__device__ __align__(16) __nv_bfloat16 g_bWt_sub [HDIM * HDIM];
__device__ __align__(16) __nv_bfloat16 g_bWt_glob[HDIM * HDIM];

// ---------------- PTX helpers ----------------
__device__ __forceinline__ void red4(float* p, float x, float y, float z, float w) {
    asm volatile("red.global.add.v4.f32 [%0], {%1, %2, %3, %4};"
                 :: "l"(p), "f"(x), "f"(y), "f"(z), "f"(w) : "memory");
}
__device__ __forceinline__ void cp_async16(uint32_t dst, const void* src) {
    asm volatile("cp.async.cg.shared.global [%0], [%1], 16;" :: "r"(dst), "l"(src) : "memory");
}
__device__ __forceinline__ void cp_commit() {
    asm volatile("cp.async.commit_group;" ::: "memory");
}
template <int N>
__device__ __forceinline__ void cp_wait() {
    asm volatile("cp.async.wait_group %0;" :: "n"(N) : "memory");
}
__device__ __forceinline__ void ldsm_x4(uint32_t& r0, uint32_t& r1, uint32_t& r2, uint32_t& r3,
                                        uint32_t addr) {
    asm volatile("ldmatrix.sync.aligned.m8n8.x4.shared.b16 {%0,%1,%2,%3}, [%4];"
                 : "=r"(r0), "=r"(r1), "=r"(r2), "=r"(r3) : "r"(addr));
}
__device__ __forceinline__ void mma_bf16(float* c, const uint32_t* a, const uint32_t* b) {
    asm volatile(
        "mma.sync.aligned.m16n8k16.row.col.f32.bf16.bf16.f32 "
        "{%0,%1,%2,%3}, {%4,%5,%6,%7}, {%8,%9}, {%0,%1,%2,%3};"
        : "+f"(c[0]), "+f"(c[1]), "+f"(c[2]), "+f"(c[3])
        : "r"(a[0]), "r"(a[1]), "r"(a[2]), "r"(a[3]), "r"(b[0]), "r"(b[1]));
}
__device__ __forceinline__ __nv_bfloat162 badd2(__nv_bfloat162 a, __nv_bfloat162 b) {
    return __hadd2(a, b);
}

// ---------------- init ----------------
// counters/sentinels only (gates the hists)
__global__ void k_zero_cnt() {
    int i = blockIdx.x * blockDim.x + threadIdx.x;   // grid covers NGLOB
    if (i < NGLOB) g_cntdeg_glob[i] = 0;
    if (i < NSUB)  g_cntdeg_sub[i]  = 0;
    if (i < HDIM) {
        g_hs_sub [NSUB  * HDIM + i] = __float2bfloat16(0.0f);
        g_hs_glob[NGLOB * HDIM + i] = __float2bfloat16(0.0f);
    }
    if (i == 0) g_gcnt = 0;
}
// accumulators (only needed before gathers)
__global__ void k_zero_rest() {
    int i = blockIdx.x * blockDim.x + threadIdx.x;   // grid covers SSEG*HDIM
    if (i < SSEG * HDIM) g_pooled[i] = 0.0f;
    if (i < 64 * HDIM)   g_gemb_part[i] = 0.0f;
    if (i < SSEG)        g_cnt[i] = 0.0f;
}
__global__ void k_hist(int* __restrict__ cnt, const int* __restrict__ ei, int E) {
    int i = blockIdx.x * blockDim.x + threadIdx.x;
    if (i < E) atomicAdd(&cnt[ei[E + i]], 1);
}

// ---- parallel padded-degree scan ----
__global__ void k_scan1(const int* __restrict__ cnt, float* __restrict__ dis,
                        int* __restrict__ bsum) {
    __shared__ int sh[8];
    int i = blockIdx.x * 256 + threadIdx.x;
    int c = cnt[i];
    dis[i] = rsqrtf((float)c + 1.0f);
    int p = (c + 3) & ~3;
    for (int o = 16; o; o >>= 1) p += __shfl_down_sync(~0u, p, o);
    if ((threadIdx.x & 31) == 0) sh[threadIdx.x >> 5] = p;
    __syncthreads();
    if (threadIdx.x < 8) {
        int v = sh[threadIdx.x];
        for (int o = 4; o; o >>= 1) v += __shfl_down_sync(0xff, v, o);
        if (threadIdx.x == 0) bsum[blockIdx.x] = v;
    }
}
__global__ void k_scan2(int* __restrict__ bsum, int NB) {
    __shared__ int sh[256];
    int t = threadIdx.x;
    int v = (t < NB) ? bsum[t] : 0;
    sh[t] = v;
    __syncthreads();
    for (int d = 1; d < 256; d <<= 1) {
        int u = (t >= d) ? sh[t - d] : 0;
        __syncthreads();
        sh[t] += u;
        __syncthreads();
    }
    if (t < NB) bsum[t] = sh[t] - v;
}
__global__ void k_scan3(const int* __restrict__ cnt, const int* __restrict__ bsum,
                        int* __restrict__ off, int* __restrict__ cur, int N) {
    __shared__ int sh[256];
    int t = threadIdx.x;
    int i = blockIdx.x * 256 + t;
    int c = cnt[i];
    int p = (c + 3) & ~3;
    sh[t] = p;
    __syncthreads();
    for (int d = 1; d < 256; d <<= 1) {
        int u = (t >= d) ? sh[t - d] : 0;
        __syncthreads();
        sh[t] += u;
        __syncthreads();
    }
    int excl = sh[t] - p + bsum[blockIdx.x];
    off[i] = excl;
    cur[i] = excl;
    if (i == N - 1) off[N] = excl + p;
}
__global__ void k_fill(int* __restrict__ csr, int* __restrict__ cur,
                       const int* __restrict__ ei, int E) {
    int i = blockIdx.x * blockDim.x + threadIdx.x;
    if (i >= E) return;
    int p = atomicAdd(&cur[ei[E + i]], 1);
    csr[p] = ei[i];
}
__global__ void k_pad(const int* __restrict__ cnt, const int* __restrict__ off,
                      int* __restrict__ csr, int N) {
    int i = blockIdx.x * blockDim.x + threadIdx.x;
    if (i >= N) return;
    int c = cnt[i], o = off[i], p = (c + 3) & ~3;
    for (int j = c; j < p; j++) csr[o + j] = N;
}

// ---------------- packs ----------------
__global__ void k_pack_A(const float* __restrict__ A, __nv_bfloat16* __restrict__ out, int M) {
    int vid = blockIdx.x * blockDim.x + threadIdx.x;
    if (vid >= M * 64) return;
    float4 v = ((const float4*)A)[vid];
    __nv_bfloat162 lo = __floats2bfloat162_rn(v.x, v.y);
    __nv_bfloat162 hi = __floats2bfloat162_rn(v.z, v.w);
    ((uint2*)out)[vid] = make_uint2(*reinterpret_cast<uint32_t*>(&lo),
                                    *reinterpret_cast<uint32_t*>(&hi));
}
__global__ void k_pack_Wt(const float* __restrict__ W, __nv_bfloat16* __restrict__ out) {
    __shared__ float tile[32][33];
    int bx = blockIdx.x * 32, by = blockIdx.y * 32;
    int tx = threadIdx.x & 31, ty = threadIdx.x >> 5;
    for (int i = 0; i < 32; i += 8)
        tile[ty + i][tx] = W[(by + ty + i) * HDIM + bx + tx];
    __syncthreads();
    for (int i = 0; i < 32; i += 8)
        out[(bx + ty + i) * HDIM + by + tx] = __float2bfloat16(tile[tx][ty + i]);
}

// ---------------- bf16 mma GEMM ----------------
#define GEMM_SMEM (4 * 16384)
__global__ __launch_bounds__(256, 2) void k_gemm_mma(
    const __nv_bfloat16* __restrict__ A,
    const __nv_bfloat16* __restrict__ Wt,
    __nv_bfloat16* __restrict__ Hs,
    float* __restrict__ Cf,
    const float* __restrict__ dis)
{
    extern __shared__ __align__(16) unsigned char smem[];
    const int tid  = threadIdx.x;
    const int lane = tid & 31, warp = tid >> 5;
    const int wm = warp & 3, wn = warp >> 2;
    const int row0 = blockIdx.x * 128, col0 = blockIdx.y * 128;
    uint32_t sbase = (uint32_t)__cvta_generic_to_shared(smem);

    float acc[2][8][4];
#pragma unroll
    for (int mt = 0; mt < 2; mt++)
#pragma unroll
        for (int nt = 0; nt < 8; nt++)
#pragma unroll
            for (int i = 0; i < 4; i++) acc[mt][nt][i] = 0.0f;

    auto load_stage = [&](int s, int kc) {
        const __nv_bfloat16* Ag = A  + (size_t)(row0)*HDIM + kc * 64;
        const __nv_bfloat16* Bg = Wt + (size_t)(col0)*HDIM + kc * 64;
        uint32_t sA = sbase + s * 16384;
        uint32_t sB = sbase + 32768 + s * 16384;
#pragma unroll
        for (int i = 0; i < 4; i++) {
            int id = tid + i * 256;
            int r = id >> 3, c = id & 7;
            uint32_t d = (uint32_t)(r * 128 + ((c ^ (r & 7)) << 4));
            cp_async16(sA + d, Ag + (size_t)r * HDIM + c * 8);
            cp_async16(sB + d, Bg + (size_t)r * HDIM + c * 8);
        }
        cp_commit();
    };

    load_stage(0, 0);
    int s = 0;
#pragma unroll 1
    for (int kc = 0; kc < 4; kc++) {
        if (kc < 3) load_stage(s ^ 1, kc + 1);
        if (kc < 3) cp_wait<1>(); else cp_wait<0>();
        __syncthreads();
        uint32_t sA = sbase + s * 16384;
        uint32_t sB = sbase + 32768 + s * 16384;
#pragma unroll
        for (int kk = 0; kk < 4; kk++) {
            uint32_t af[2][4];
#pragma unroll
            for (int mt = 0; mt < 2; mt++) {
                int r = wm * 32 + mt * 16 + (lane & 15);
                int c = kk * 2 + (lane >> 4);
                ldsm_x4(af[mt][0], af[mt][1], af[mt][2], af[mt][3],
                        sA + r * 128 + ((c ^ (r & 7)) << 4));
            }
            uint32_t bf[8][2];
#pragma unroll
            for (int p = 0; p < 4; p++) {
                int r = wn * 64 + p * 16 + ((lane >> 4) << 3) + (lane & 7);
                int c = kk * 2 + ((lane >> 3) & 1);
                ldsm_x4(bf[2 * p][0], bf[2 * p][1], bf[2 * p + 1][0], bf[2 * p + 1][1],
                        sB + r * 128 + ((c ^ (r & 7)) << 4));
            }
#pragma unroll
            for (int mt = 0; mt < 2; mt++)
#pragma unroll
                for (int nt = 0; nt < 8; nt++)
                    mma_bf16(acc[mt][nt], af[mt], bf[nt]);
        }
        __syncthreads();
        s ^= 1;
    }

    const int g = lane >> 2, t4 = lane & 3;
#pragma unroll
    for (int mt = 0; mt < 2; mt++) {
        int r_lo = row0 + wm * 32 + mt * 16 + g;
        int r_hi = r_lo + 8;
        if (dis) {
            float dlo = dis[r_lo], dhi = dis[r_hi];
#pragma unroll
            for (int nt = 0; nt < 8; nt++) {
                int col = col0 + wn * 64 + nt * 8 + 2 * t4;
                __nv_bfloat162 lo = __floats2bfloat162_rn(acc[mt][nt][0] * dlo,
                                                          acc[mt][nt][1] * dlo);
                __nv_bfloat162 hi = __floats2bfloat162_rn(acc[mt][nt][2] * dhi,
                                                          acc[mt][nt][3] * dhi);
                *(__nv_bfloat162*)&Hs[(size_t)r_lo * HDIM + col] = lo;
                *(__nv_bfloat162*)&Hs[(size_t)r_hi * HDIM + col] = hi;
            }
        } else {
#pragma unroll
            for (int nt = 0; nt < 8; nt++) {
                int col = col0 + wn * 64 + nt * 8 + 2 * t4;
                *(float2*)&Cf[(size_t)r_lo * HDIM + col] =
                    make_float2(acc[mt][nt][0], acc[mt][nt][1]);
                *(float2*)&Cf[(size_t)r_hi * HDIM + col] =
                    make_float2(acc[mt][nt][2], acc[mt][nt][3]);
            }
        }
    }
}

// ---------------- CSR gather + fused epilogues ----------------
__global__ __launch_bounds__(256) void k_gather_sub(
    const int* __restrict__ batch, const float* __restrict__ bias)
{
    const int lane = threadIdx.x & 31, grp = threadIdx.x >> 5;
    const uint4* H = (const uint4*)g_hs_sub;
    float4 b0 = ((const float4*)bias)[lane * 2];
    float4 b1 = ((const float4*)bias)[lane * 2 + 1];
#pragma unroll 1
    for (int it = 0; it < 4; it++) {
        int n = blockIdx.x * 32 + it * 8 + grp;
        int o0 = g_off_sub[n] >> 2, o1 = g_off_sub[n + 1] >> 2;
        uint4 a = H[(size_t)n * 32 + lane];
        __nv_bfloat162 A0 = *(__nv_bfloat162*)&a.x, A1 = *(__nv_bfloat162*)&a.y,
                       A2 = *(__nv_bfloat162*)&a.z, A3 = *(__nv_bfloat162*)&a.w;
#pragma unroll 1
        for (int k = o0; k < o1; k++) {
            int4 s4 = ((const int4*)g_csr_sub)[k];
            uint4 v;
            v = H[(size_t)s4.x * 32 + lane];
            A0 = badd2(A0, *(__nv_bfloat162*)&v.x); A1 = badd2(A1, *(__nv_bfloat162*)&v.y);
            A2 = badd2(A2, *(__nv_bfloat162*)&v.z); A3 = badd2(A3, *(__nv_bfloat162*)&v.w);
            v = H[(size_t)s4.y * 32 + lane];
            A0 = badd2(A0, *(__nv_bfloat162*)&v.x); A1 = badd2(A1, *(__nv_bfloat162*)&v.y);
            A2 = badd2(A2, *(__nv_bfloat162*)&v.z); A3 = badd2(A3, *(__nv_bfloat162*)&v.w);
            v = H[(size_t)s4.z * 32 + lane];
            A0 = badd2(A0, *(__nv_bfloat162*)&v.x); A1 = badd2(A1, *(__nv_bfloat162*)&v.y);
            A2 = badd2(A2, *(__nv_bfloat162*)&v.z); A3 = badd2(A3, *(__nv_bfloat162*)&v.w);
            v = H[(size_t)s4.w * 32 + lane];
            A0 = badd2(A0, *(__nv_bfloat162*)&v.x); A1 = badd2(A1, *(__nv_bfloat162*)&v.y);
            A2 = badd2(A2, *(__nv_bfloat162*)&v.z); A3 = badd2(A3, *(__nv_bfloat162*)&v.w);
        }
        float d = g_dis_sub[n];
        float2 f0 = __bfloat1622float2(A0), f1 = __bfloat1622float2(A1);
        float2 f2 = __bfloat1622float2(A2), f3 = __bfloat1622float2(A3);
        float* dst = g_pooled + (size_t)batch[n] * HDIM + lane * 8;
        red4(dst,
             fmaxf(fmaf(f0.x, d, b0.x), 0.0f), fmaxf(fmaf(f0.y, d, b0.y), 0.0f),
             fmaxf(fmaf(f1.x, d, b0.z), 0.0f), fmaxf(fmaf(f1.y, d, b0.w), 0.0f));
        red4(dst + 4,
             fmaxf(fmaf(f2.x, d, b1.x), 0.0f), fmaxf(fmaf(f2.y, d, b1.y), 0.0f),
             fmaxf(fmaf(f3.x, d, b1.z), 0.0f), fmaxf(fmaf(f3.y, d, b1.w), 0.0f));
    }
}

__global__ __launch_bounds__(256) void k_gather_glob(
    const int* __restrict__ batch, const float* __restrict__ bias)
{
    const int lane = threadIdx.x & 31, grp = threadIdx.x >> 5;
    const uint4* H = (const uint4*)g_hs_glob;
    float4 b0 = ((const float4*)bias)[lane * 2];
    float4 b1 = ((const float4*)bias)[lane * 2 + 1];
    float r0 = 0, r1 = 0, r2 = 0, r3 = 0, r4 = 0, r5 = 0, r6 = 0, r7 = 0;
    int cloc = 0;
#pragma unroll 1
    for (int it = 0; it < 4; it++) {
        int n = blockIdx.x * 32 + it * 8 + grp;
        int o0 = g_off_glob[n] >> 2, o1 = g_off_glob[n + 1] >> 2;
        uint4 a = H[(size_t)n * 32 + lane];
        __nv_bfloat162 A0 = *(__nv_bfloat162*)&a.x, A1 = *(__nv_bfloat162*)&a.y,
                       A2 = *(__nv_bfloat162*)&a.z, A3 = *(__nv_bfloat162*)&a.w;
#pragma unroll 1
        for (int k = o0; k < o1; k++) {
            int4 s4 = ((const int4*)g_csr_glob)[k];
            uint4 v;
            v = H[(size_t)s4.x * 32 + lane];
            A0 = badd2(A0, *(__nv_bfloat162*)&v.x); A1 = badd2(A1, *(__nv_bfloat162*)&v.y);
            A2 = badd2(A2, *(__nv_bfloat162*)&v.z); A3 = badd2(A3, *(__nv_bfloat162*)&v.w);
            v = H[(size_t)s4.y * 32 + lane];
            A0 = badd2(A0, *(__nv_bfloat162*)&v.x); A1 = badd2(A1, *(__nv_bfloat162*)&v.y);
            A2 = badd2(A2, *(__nv_bfloat162*)&v.z); A3 = badd2(A3, *(__nv_bfloat162*)&v.w);
            v = H[(size_t)s4.z * 32 + lane];
            A0 = badd2(A0, *(__nv_bfloat162*)&v.x); A1 = badd2(A1, *(__nv_bfloat162*)&v.y);
            A2 = badd2(A2, *(__nv_bfloat162*)&v.z); A3 = badd2(A3, *(__nv_bfloat162*)&v.w);
            v = H[(size_t)s4.w * 32 + lane];
            A0 = badd2(A0, *(__nv_bfloat162*)&v.x); A1 = badd2(A1, *(__nv_bfloat162*)&v.y);
            A2 = badd2(A2, *(__nv_bfloat162*)&v.z); A3 = badd2(A3, *(__nv_bfloat162*)&v.w);
        }
        if (batch[n] == 0) {
            float d = g_dis_glob[n];
            float2 f0 = __bfloat1622float2(A0), f1 = __bfloat1622float2(A1);
            float2 f2 = __bfloat1622float2(A2), f3 = __bfloat1622float2(A3);
            r0 += fmaxf(fmaf(f0.x, d, b0.x), 0.0f);
            r1 += fmaxf(fmaf(f0.y, d, b0.y), 0.0f);
            r2 += fmaxf(fmaf(f1.x, d, b0.z), 0.0f);
            r3 += fmaxf(fmaf(f1.y, d, b0.w), 0.0f);
            r4 += fmaxf(fmaf(f2.x, d, b1.x), 0.0f);
            r5 += fmaxf(fmaf(f2.y, d, b1.y), 0.0f);
            r6 += fmaxf(fmaf(f3.x, d, b1.z), 0.0f);
            r7 += fmaxf(fmaf(f3.y, d, b1.w), 0.0f);
            cloc++;
        }
    }
    float* dst = g_gemb_part + (size_t)(blockIdx.x & 63) * HDIM + lane * 8;
    red4(dst, r0, r1, r2, r3);
    red4(dst + 4, r4, r5, r6, r7);
    if (lane == 0) atomicAdd(&g_gcnt, cloc);
}

// ---------------- misc ----------------
__global__ void k_cnt_sub(const int* __restrict__ batch, int N) {
    int i = blockIdx.x * blockDim.x + threadIdx.x;
    if (i < N) atomicAdd(&g_cnt[batch[i]], 1.0f);
}
__global__ void k_pool_div() {
    int idx = blockIdx.x * blockDim.x + threadIdx.x;
    if (idx >= SSEG * HDIM) return;
    int s = idx >> 8;
    g_pooled[idx] /= fmaxf(g_cnt[s], 1.0f);
}
__global__ void k_inject(const int* __restrict__ sub_index) {
    int idx = blockIdx.x * blockDim.x + threadIdx.x;
    if (idx >= SSEG * 128) return;
    int s = idx >> 7, c2 = idx & 127;
    int node = sub_index[s];
    float d = g_dis_glob[node];
    __nv_bfloat162* hp = (__nv_bfloat162*)g_hs_glob + (size_t)node * 128 + c2;
    float2 h = __bfloat1622float2(*hp);
    const float* p = g_p2 + (size_t)s * HDIM + c2 * 2;
    *hp = __floats2bfloat162_rn(fmaf(p[0], d, h.x), fmaf(p[1], d, h.y));
}
__global__ void k_final(const float* __restrict__ fc_W, const float* __restrict__ fc_b,
                        float* __restrict__ out) {
    __shared__ float sg[HDIM];
    int t = threadIdx.x;
    float s = 0.0f;
#pragma unroll 8
    for (int p = 0; p < 64; p++) s += g_gemb_part[p * HDIM + t];
    sg[t] = s / fmaxf((float)g_gcnt, 1.0f);
    __syncthreads();
    float acc = fc_b[t];
    const float* wr = fc_W + (size_t)t * HDIM;
#pragma unroll 8
    for (int h = 0; h < HDIM; h++) acc = fmaf(sg[h], wr[h], acc);
    out[t] = acc;
}

// ---------------- host launcher ----------------
extern "C" void kernel_launch(void* const* d_in, const int* in_sizes, int n_in,
                              void* d_out, int out_size) {
    const float* x_sub      = (const float*)d_in[0];
    const int*   ei_sub     = (const int*)  d_in[1];
    const int*   batch_sub  = (const int*)  d_in[2];
    const int*   sub_index  = (const int*)  d_in[3];
    const float* x_glob     = (const float*)d_in[4];
    const int*   ei_glob    = (const int*)  d_in[5];
    const int*   batch_glob = (const int*)  d_in[6];
    const float* W_sub      = (const float*)d_in[7];
    const float* b_sub      = (const float*)d_in[8];
    const float* W_glob     = (const float*)d_in[9];
    const float* b_glob     = (const float*)d_in[10];
    const float* fc_W       = (const float*)d_in[11];
    const float* fc_b       = (const float*)d_in[12];
    float* out = (float*)d_out;

    const int E_sub  = in_sizes[1] / 2;
    const int E_glob = in_sizes[5] / 2;

    static bool init = false;
    static float *p_dis_sub, *p_dis_glob, *p_pooled, *p_p2;
    static int *p_cd_sub, *p_cd_glob, *p_off_sub, *p_off_glob, *p_cur_sub, *p_cur_glob,
               *p_csr_sub, *p_csr_glob, *p_bs_sub, *p_bs_glob;
    static __nv_bfloat16 *pb_a_sub, *pb_a_glob, *pb_a_pool, *pb_wt_sub, *pb_wt_glob,
                         *p_hs_sub, *p_hs_glob;
    static cudaStream_t s2, s3, s4;
    static cudaEvent_t eStart, eZ, eDs, eDg, ePWg, eCSRs, eCSRg, eG;
    if (!init) {
        init = true;
        cudaGetSymbolAddress((void**)&p_dis_sub,  g_dis_sub);
        cudaGetSymbolAddress((void**)&p_dis_glob, g_dis_glob);
        cudaGetSymbolAddress((void**)&p_pooled,   g_pooled);
        cudaGetSymbolAddress((void**)&p_p2,       g_p2);
        cudaGetSymbolAddress((void**)&p_cd_sub,   g_cntdeg_sub);
        cudaGetSymbolAddress((void**)&p_cd_glob,  g_cntdeg_glob);
        cudaGetSymbolAddress((void**)&p_off_sub,  g_off_sub);
        cudaGetSymbolAddress((void**)&p_off_glob, g_off_glob);
        cudaGetSymbolAddress((void**)&p_cur_sub,  g_cur_sub);
        cudaGetSymbolAddress((void**)&p_cur_glob, g_cur_glob);
        cudaGetSymbolAddress((void**)&p_csr_sub,  g_csr_sub);
        cudaGetSymbolAddress((void**)&p_csr_glob, g_csr_glob);
        cudaGetSymbolAddress((void**)&p_bs_sub,   g_bsum_sub);
        cudaGetSymbolAddress((void**)&p_bs_glob,  g_bsum_glob);
        cudaGetSymbolAddress((void**)&pb_a_sub,   g_bA_sub);
        cudaGetSymbolAddress((void**)&pb_a_glob,  g_bA_glob);
        cudaGetSymbolAddress((void**)&pb_a_pool,  g_bA_pool);
        cudaGetSymbolAddress((void**)&pb_wt_sub,  g_bWt_sub);
        cudaGetSymbolAddress((void**)&pb_wt_glob, g_bWt_glob);
        cudaGetSymbolAddress((void**)&p_hs_sub,   g_hs_sub);
        cudaGetSymbolAddress((void**)&p_hs_glob,  g_hs_glob);
        cudaFuncSetAttribute(k_gemm_mma, cudaFuncAttributeMaxDynamicSharedMemorySize, GEMM_SMEM);
        cudaStreamCreateWithFlags(&s2, cudaStreamNonBlocking);
        cudaStreamCreateWithFlags(&s3, cudaStreamNonBlocking);
        cudaStreamCreateWithFlags(&s4, cudaStreamNonBlocking);
        cudaEventCreateWithFlags(&eStart, cudaEventDisableTiming);
        cudaEventCreateWithFlags(&eZ,     cudaEventDisableTiming);
        cudaEventCreateWithFlags(&eDs,    cudaEventDisableTiming);
        cudaEventCreateWithFlags(&eDg,    cudaEventDisableTiming);
        cudaEventCreateWithFlags(&ePWg,   cudaEventDisableTiming);
        cudaEventCreateWithFlags(&eCSRs,  cudaEventDisableTiming);
        cudaEventCreateWithFlags(&eCSRg,  cudaEventDisableTiming);
        cudaEventCreateWithFlags(&eG,     cudaEventDisableTiming);
    }

    // ---- fork ----
    cudaEventRecord(eStart, 0);
    cudaStreamWaitEvent(s2, eStart, 0);
    cudaStreamWaitEvent(s3, eStart, 0);
    cudaStreamWaitEvent(s4, eStart, 0);

    // s0: zero counters (gates hists), then accumulator zeroing
    k_zero_cnt <<<NGLOB / 256, 256>>>();
    cudaEventRecord(eZ, 0);
    k_zero_rest<<<(SSEG * HDIM + 255) / 256, 256>>>();

    // ---- s2: glob CSR build ----
    cudaStreamWaitEvent(s2, eZ, 0);
    k_hist <<<(E_glob + 255) / 256, 256, 0, s2>>>(p_cd_glob, ei_glob, E_glob);
    k_scan1<<<NGLOB / 256, 256, 0, s2>>>(p_cd_glob, p_dis_glob, p_bs_glob);
    cudaEventRecord(eDg, s2);
    k_scan2<<<1, 256, 0, s2>>>(p_bs_glob, NGLOB / 256);
    k_scan3<<<NGLOB / 256, 256, 0, s2>>>(p_cd_glob, p_bs_glob, p_off_glob, p_cur_glob, NGLOB);
    k_fill <<<(E_glob + 255) / 256, 256, 0, s2>>>(p_csr_glob, p_cur_glob, ei_glob, E_glob);
    k_pad  <<<NGLOB / 256, 256, 0, s2>>>(p_cd_glob, p_off_glob, p_csr_glob, NGLOB);
    cudaEventRecord(eCSRg, s2);

    // ---- s3: glob pack + GEMM ----
    k_pack_Wt<<<dim3(8, 8), 256, 0, s3>>>(W_glob, pb_wt_glob);
    cudaEventRecord(ePWg, s3);
    k_pack_A <<<(NGLOB * 64 + 255) / 256, 256, 0, s3>>>(x_glob, pb_a_glob, NGLOB);
    cudaStreamWaitEvent(s3, eDg, 0);
    k_gemm_mma<<<dim3(NGLOB / 128, 2), 256, GEMM_SMEM, s3>>>(pb_a_glob, pb_wt_glob,
                                                             p_hs_glob, nullptr, p_dis_glob);
    cudaEventRecord(eG, s3);

    // ---- s4: sub CSR build ----
    cudaStreamWaitEvent(s4, eZ, 0);
    k_hist <<<(E_sub + 255) / 256, 256, 0, s4>>>(p_cd_sub, ei_sub, E_sub);
    k_scan1<<<NSUB / 256, 256, 0, s4>>>(p_cd_sub, p_dis_sub, p_bs_sub);
    cudaEventRecord(eDs, s4);
    k_scan2<<<1, 256, 0, s4>>>(p_bs_sub, NSUB / 256);
    k_scan3<<<NSUB / 256, 256, 0, s4>>>(p_cd_sub, p_bs_sub, p_off_sub, p_cur_sub, NSUB);
    k_fill <<<(E_sub + 255) / 256, 256, 0, s4>>>(p_csr_sub, p_cur_sub, ei_sub, E_sub);
    k_pad  <<<NSUB / 256, 256, 0, s4>>>(p_cd_sub, p_off_sub, p_csr_sub, NSUB);
    cudaEventRecord(eCSRs, s4);

    // ---- s0: sub pack/GEMM/gather + pooled GEMM ----
    k_pack_Wt<<<dim3(8, 8), 256>>>(W_sub, pb_wt_sub);
    k_pack_A <<<(NSUB * 64 + 255) / 256, 256>>>(x_sub, pb_a_sub, NSUB);
    k_cnt_sub<<<(NSUB + 255) / 256, 256>>>(batch_sub, NSUB);
    cudaStreamWaitEvent(0, eDs, 0);
    k_gemm_mma<<<dim3(NSUB / 128, 2), 256, GEMM_SMEM>>>(pb_a_sub, pb_wt_sub,
                                                        p_hs_sub, nullptr, p_dis_sub);
    cudaStreamWaitEvent(0, eCSRs, 0);
    k_gather_sub<<<NSUB / 32, 256>>>(batch_sub, b_sub);
    k_pool_div<<<(SSEG * HDIM + 255) / 256, 256>>>();
    k_pack_A <<<(SSEG * 64 + 255) / 256, 256>>>(p_pooled, pb_a_pool, SSEG);
    cudaStreamWaitEvent(0, ePWg, 0);
    k_gemm_mma<<<dim3(SSEG / 128, 2), 256, GEMM_SMEM>>>(pb_a_pool, pb_wt_glob,
                                                        nullptr, p_p2, nullptr);

    // ---- join: inject + global gather + final ----
    cudaStreamWaitEvent(0, eG, 0);
    k_inject<<<(SSEG * 128 + 255) / 256, 256>>>(sub_index);
    cudaStreamWaitEvent(0, eCSRg, 0);
    k_gather_glob<<<NGLOB / 32, 256>>>(batch_glob, b_glob);
    k_final<<<1, 256>>>(fc_W, fc_b, out);
}